// round 1
// baseline (speedup 1.0000x reference)
#include <cuda_runtime.h>
#include <cuda_bf16.h>
#include <math.h>

// Problem constants
#define BB    4
#define NTOK  32768          // B*N
#define CC    256
#define HH    8
#define HD    32
#define LL    64
#define NBLK  512            // B * NB
#define EGH   16

// ---------------- scratch (device globals; no allocs allowed) ----------------
__device__ float g_qkv[(size_t)NTOK * 768];          // [token][0:256 q | 256:512 k | 512:768 v]
__device__ float g_gate[(size_t)NBLK * 64 * 64 * 8]; // [blk][q][k][h]
__device__ float g_xm[(size_t)NTOK * CC];            // attention output

// ---------------- SGEMM: Y[M][Nn] = X[M][K] @ W[Nn][K]^T + bias -------------
#define TM 128
#define TN 128
#define TK 8

__global__ __launch_bounds__(256) void sgemm_bias(
    const float* __restrict__ X, const float* __restrict__ W,
    const float* __restrict__ bias, float* __restrict__ Y,
    int M, int Nn, int K)
{
    __shared__ float As[TK][TM];
    __shared__ float Bs[TK][TN];
    int tid = threadIdx.x;
    int tx = tid & 15, ty = tid >> 4;
    int m0 = blockIdx.y * TM;
    int n0 = blockIdx.x * TN;

    float acc[8][8];
    #pragma unroll
    for (int i = 0; i < 8; i++)
        #pragma unroll
        for (int j = 0; j < 8; j++) acc[i][j] = 0.0f;

    int lr = tid >> 1;           // 0..127
    int lk = (tid & 1) * 4;      // 0 or 4
    const float* xg = X + (size_t)(m0 + lr) * K + lk;
    const float* wg = W + (size_t)(n0 + lr) * K + lk;

    for (int k0 = 0; k0 < K; k0 += TK) {
        float4 av = *(const float4*)(xg + k0);
        float4 bv = *(const float4*)(wg + k0);
        As[lk + 0][lr] = av.x; As[lk + 1][lr] = av.y;
        As[lk + 2][lr] = av.z; As[lk + 3][lr] = av.w;
        Bs[lk + 0][lr] = bv.x; Bs[lk + 1][lr] = bv.y;
        Bs[lk + 2][lr] = bv.z; Bs[lk + 3][lr] = bv.w;
        __syncthreads();
        #pragma unroll
        for (int kk = 0; kk < TK; kk++) {
            float a[8], b[8];
            *(float4*)(a)     = *(const float4*)&As[kk][ty * 8];
            *(float4*)(a + 4) = *(const float4*)&As[kk][ty * 8 + 4];
            *(float4*)(b)     = *(const float4*)&Bs[kk][tx * 8];
            *(float4*)(b + 4) = *(const float4*)&Bs[kk][tx * 8 + 4];
            #pragma unroll
            for (int i = 0; i < 8; i++)
                #pragma unroll
                for (int j = 0; j < 8; j++) acc[i][j] += a[i] * b[j];
        }
        __syncthreads();
    }

    #pragma unroll
    for (int i = 0; i < 8; i++) {
        int row = m0 + ty * 8 + i;
        float* yr = Y + (size_t)row * Nn + n0 + tx * 8;
        float4 o0, o1;
        o0.x = acc[i][0] + bias[n0 + tx * 8 + 0];
        o0.y = acc[i][1] + bias[n0 + tx * 8 + 1];
        o0.z = acc[i][2] + bias[n0 + tx * 8 + 2];
        o0.w = acc[i][3] + bias[n0 + tx * 8 + 3];
        o1.x = acc[i][4] + bias[n0 + tx * 8 + 4];
        o1.y = acc[i][5] + bias[n0 + tx * 8 + 5];
        o1.z = acc[i][6] + bias[n0 + tx * 8 + 6];
        o1.w = acc[i][7] + bias[n0 + tx * 8 + 7];
        *(float4*)(yr)     = o0;
        *(float4*)(yr + 4) = o1;
    }
}

// ---------------- gate kernel: g[blk][q][k][h], masked --------------------
__global__ __launch_bounds__(256) void gate_kernel(
    const float* __restrict__ mask_g, const float* __restrict__ ef,
    const float* __restrict__ w1, const float* __restrict__ b1,
    const float* __restrict__ w2, const float* __restrict__ b2)
{
    __shared__ float sm[64 * 64];
    __shared__ float sw1[64], sb1[16], sw2[128], sb2[8];
    int blk = blockIdx.x;
    int tid = threadIdx.x;

    const float* mbase = mask_g + (size_t)blk * 4096;
    #pragma unroll
    for (int i = 0; i < 16; i++) sm[tid + i * 256] = mbase[tid + i * 256];
    if (tid < 64)  sw1[tid] = w1[tid];
    if (tid < 16)  sb1[tid] = b1[tid];
    if (tid < 128) sw2[tid] = w2[tid];
    if (tid < 8)   sb2[tid] = b2[tid];
    __syncthreads();

    if (tid < 64) {                                  // diagonal fix-up
        float s = 0.0f;
        for (int k = 0; k < 64; k++) s += sm[tid * 64 + k];
        if (s < 1.0f) sm[tid * 64 + tid] = 1.0f;
    }
    __syncthreads();

    for (int it = 0; it < 16; it++) {
        int idx = tid + it * 256;                    // 0..4095
        int q = idx >> 6, k = idx & 63;
        float m = sm[idx];
        float out[8];
        if (m == 0.0f) {
            #pragma unroll
            for (int h = 0; h < 8; h++) out[h] = 0.0f;
        } else {
            float e0, e1, e2, e3;
            if (q == k) { e0 = e1 = e2 = 0.0f; e3 = 1.0f; }
            else {
                float4 ev = *(const float4*)(ef + ((size_t)blk * 4096 + idx) * 4);
                e0 = ev.x; e1 = ev.y; e2 = ev.z; e3 = ev.w;
            }
            float hh[16];
            #pragma unroll
            for (int j = 0; j < 16; j++) {
                float t = sb1[j] + sw1[j * 4] * e0 + sw1[j * 4 + 1] * e1
                        + sw1[j * 4 + 2] * e2 + sw1[j * 4 + 3] * e3;
                hh[j] = 0.5f * t * (1.0f + erff(t * 0.70710678118654752f));
            }
            #pragma unroll
            for (int h = 0; h < 8; h++) {
                float s = sb2[h];
                #pragma unroll
                for (int j = 0; j < 16; j++) s += sw2[h * 16 + j] * hh[j];
                out[h] = s;
            }
        }
        float* gp = g_gate + ((size_t)blk * 4096 + idx) * 8;
        *(float4*)(gp)     = make_float4(out[0], out[1], out[2], out[3]);
        *(float4*)(gp + 4) = make_float4(out[4], out[5], out[6], out[7]);
    }
}

// ---------------- attention kernel: one CTA per (b, block) ----------------
// dyn smem: Ks[64*256] Vs[64*256] Sb[64*65] Sc[64*65]  = 164352 bytes
#define ATTN_SMEM ((64 * 256 * 2 + 64 * 65 * 2) * 4)

__global__ __launch_bounds__(256) void attn_kernel(
    const float* __restrict__ mask_g, const float* __restrict__ ef)
{
    extern __shared__ float smem[];
    float* Ks = smem;
    float* Vs = Ks + 64 * 256;
    float* Sb = Vs + 64 * 256;     // bias-or-(-1e30) per (q,k), stride 65
    float* Sc = Sb + 64 * 65;      // scores / probs, stride 65

    int blk = blockIdx.x;
    int tid = threadIdx.x;
    int t0 = blk * 64;

    // stage K, V
    #pragma unroll
    for (int i = 0; i < 16; i++) {
        int v = tid + i * 256;               // float4 index, 0..4095
        int l = v >> 6, c4 = (v & 63) * 4;
        const float* base = g_qkv + (size_t)(t0 + l) * 768;
        *(float4*)&Ks[l * 256 + c4] = *(const float4*)(base + 256 + c4);
        *(float4*)&Vs[l * 256 + c4] = *(const float4*)(base + 512 + c4);
    }
    // stage mask into Sb
    #pragma unroll
    for (int i = 0; i < 16; i++) {
        int idx = tid + i * 256;
        Sb[(idx >> 6) * 65 + (idx & 63)] = mask_g[(size_t)blk * 4096 + idx];
    }
    __syncthreads();
    if (tid < 64) {                          // diagonal fix-up
        float s = 0.0f;
        for (int k = 0; k < 64; k++) s += Sb[tid * 65 + k];
        if (s < 1.0f) Sb[tid * 65 + tid] = 1.0f;
    }
    __syncthreads();
    // fold mask + physics bias into Sb
    #pragma unroll
    for (int i = 0; i < 16; i++) {
        int idx = tid + i * 256;
        int q = idx >> 6, k = idx & 63;
        float m = Sb[q * 65 + k];
        float bias = (q == k) ? 1.0f : ef[((size_t)blk * 4096 + idx) * 4 + 3];
        Sb[q * 65 + k] = (m == 0.0f) ? -1e30f : bias;
    }

    const float scale = 0.17677669529663687f;   // 32^-0.5

    for (int h = 0; h < 8; h++) {
        // ---- scores: thread handles (q = tid&63, 16 k's) ----
        int q = tid & 63;
        int kb = (tid >> 6) << 4;
        float4 qr[8];
        {
            const float* qg = g_qkv + (size_t)(t0 + q) * 768 + h * 32;
            #pragma unroll
            for (int d = 0; d < 8; d++) qr[d] = *(const float4*)(qg + d * 4);
        }
        __syncthreads();   // prev PV done reading Sc; Sb ready on first iter
        #pragma unroll 4
        for (int kk = 0; kk < 16; kk++) {
            int k = kb + kk;
            const float4* kr = (const float4*)&Ks[k * 256 + h * 32];
            float acc = 0.0f;
            #pragma unroll
            for (int d = 0; d < 8; d++) {
                float4 kv = kr[d];
                acc += qr[d].x * kv.x + qr[d].y * kv.y
                     + qr[d].z * kv.z + qr[d].w * kv.w;
            }
            Sc[q * 65 + k] = acc * scale + Sb[q * 65 + k];
        }
        __syncthreads();

        // ---- softmax + gate add: 4 lanes per row ----
        {
            int qq = tid >> 2, quad = tid & 3;
            float vals[16];
            float vmax = -3.0e38f;
            #pragma unroll
            for (int i = 0; i < 16; i++) {
                vals[i] = Sc[qq * 65 + quad * 16 + i];
                vmax = fmaxf(vmax, vals[i]);
            }
            vmax = fmaxf(vmax, __shfl_xor_sync(0xffffffffu, vmax, 1));
            vmax = fmaxf(vmax, __shfl_xor_sync(0xffffffffu, vmax, 2));
            float ssum = 0.0f;
            #pragma unroll
            for (int i = 0; i < 16; i++) {
                float e = __expf(vals[i] - vmax);
                vals[i] = e;
                ssum += e;
            }
            ssum += __shfl_xor_sync(0xffffffffu, ssum, 1);
            ssum += __shfl_xor_sync(0xffffffffu, ssum, 2);
            float inv = 1.0f / ssum;
            const float* gb = g_gate + ((size_t)blk * 4096 + qq * 64) * 8 + h;
            #pragma unroll
            for (int i = 0; i < 16; i++) {
                int k = quad * 16 + i;
                Sc[qq * 65 + k] = vals[i] * inv + gb[k * 8];
            }
        }
        __syncthreads();

        // ---- PV: thread handles (q = tid&63, 8 d's) ----
        {
            int dc = (tid >> 6) << 3;
            float acc[8];
            #pragma unroll
            for (int j = 0; j < 8; j++) acc[j] = 0.0f;
            #pragma unroll 4
            for (int k = 0; k < 64; k++) {
                float p = Sc[q * 65 + k];
                const float4* vr = (const float4*)&Vs[k * 256 + h * 32 + dc];
                float4 v0 = vr[0], v1 = vr[1];
                acc[0] += p * v0.x; acc[1] += p * v0.y;
                acc[2] += p * v0.z; acc[3] += p * v0.w;
                acc[4] += p * v1.x; acc[5] += p * v1.y;
                acc[6] += p * v1.z; acc[7] += p * v1.w;
            }
            float* og = g_xm + (size_t)(t0 + q) * 256 + h * 32 + dc;
            *(float4*)(og)     = make_float4(acc[0], acc[1], acc[2], acc[3]);
            *(float4*)(og + 4) = make_float4(acc[4], acc[5], acc[6], acc[7]);
        }
    }
}

// ---------------- launch ----------------
extern "C" void kernel_launch(void* const* d_in, const int* in_sizes, int n_in,
                              void* d_out, int out_size)
{
    const float* x      = (const float*)d_in[0];
    const float* amask  = (const float*)d_in[1];
    const float* efeat  = (const float*)d_in[2];
    const float* qkv_w  = (const float*)d_in[3];
    const float* qkv_b  = (const float*)d_in[4];
    const float* proj_w = (const float*)d_in[5];
    const float* proj_b = (const float*)d_in[6];
    const float* eg_w1  = (const float*)d_in[7];
    const float* eg_b1  = (const float*)d_in[8];
    const float* eg_w2  = (const float*)d_in[9];
    const float* eg_b2  = (const float*)d_in[10];
    float* out = (float*)d_out;

    void* p_qkv = nullptr;
    void* p_xm  = nullptr;
    cudaGetSymbolAddress(&p_qkv, g_qkv);
    cudaGetSymbolAddress(&p_xm, g_xm);

    cudaFuncSetAttribute(attn_kernel,
                         cudaFuncAttributeMaxDynamicSharedMemorySize, ATTN_SMEM);

    // 1) QKV projection: [32768,768] = x[32768,256] @ qkv_w^T
    sgemm_bias<<<dim3(768 / TN, NTOK / TM), 256>>>(
        x, qkv_w, qkv_b, (float*)p_qkv, NTOK, 768, CC);

    // 2) edge gate (independent of qkv)
    gate_kernel<<<NBLK, 256>>>(amask, efeat, eg_w1, eg_b1, eg_w2, eg_b2);

    // 3) block attention
    attn_kernel<<<NBLK, 256, ATTN_SMEM>>>(amask, efeat);

    // 4) output projection
    sgemm_bias<<<dim3(CC / TN, NTOK / TM), 256>>>(
        (const float*)p_xm, proj_w, proj_b, out, NTOK, CC, CC);
}

// round 3
// speedup vs baseline: 1.6439x; 1.6439x over previous
#include <cuda_runtime.h>
#include <cuda_bf16.h>
#include <math.h>
#include <cstdint>

// Problem constants
#define BB    4
#define NTOK  32768          // B*N
#define CC    256
#define HH    8
#define HD    32
#define LL    64
#define NBLK  512            // B * NB
#define EGH   16

// ---------------- scratch (device globals; no allocs allowed) ----------------
__device__ float g_qkv[(size_t)NTOK * 768];          // [token][0:256 q | 256:512 k | 512:768 v]
__device__ float g_gate[(size_t)NBLK * 64 * 64 * 8]; // [blk][q][k][h]
__device__ float g_xm[(size_t)NTOK * CC];            // attention output

// ======================= PTX helpers (sm_80-compatible) =======================
__device__ __forceinline__ uint32_t smem_to_u32(const void* p) {
    uint32_t a;
    asm("{ .reg .u64 t; cvta.to.shared.u64 t, %1; cvt.u32.u64 %0, t; }"
        : "=r"(a) : "l"(p));
    return a;
}

__device__ __forceinline__ void cp_async16(uint32_t smem_addr, const void* gptr) {
    asm volatile("cp.async.cg.shared.global [%0], [%1], 16;"
                 :: "r"(smem_addr), "l"(gptr));
}
#define CP_COMMIT() asm volatile("cp.async.commit_group;" ::: "memory")
#define CP_WAIT(n)  asm volatile("cp.async.wait_group %0;" :: "n"(n) : "memory")

__device__ __forceinline__ void ldsm4(uint32_t& r0, uint32_t& r1, uint32_t& r2,
                                      uint32_t& r3, uint32_t addr) {
    asm volatile("ldmatrix.sync.aligned.m8n8.x4.shared.b16 {%0,%1,%2,%3}, [%4];"
                 : "=r"(r0), "=r"(r1), "=r"(r2), "=r"(r3) : "r"(addr));
}

__device__ __forceinline__ uint32_t to_tf32(uint32_t x) {
    uint32_t y;
    asm("cvt.rna.tf32.f32 %0, %1;" : "=r"(y) : "r"(x));
    return y;
}

__device__ __forceinline__ void mma_tf32(float& c0, float& c1, float& c2, float& c3,
                                         uint32_t a0, uint32_t a1, uint32_t a2, uint32_t a3,
                                         uint32_t b0, uint32_t b1) {
    asm volatile(
        "mma.sync.aligned.m16n8k8.row.col.f32.tf32.tf32.f32 "
        "{%0,%1,%2,%3}, {%4,%5,%6,%7}, {%8,%9}, {%0,%1,%2,%3};"
        : "+f"(c0), "+f"(c1), "+f"(c2), "+f"(c3)
        : "r"(a0), "r"(a1), "r"(a2), "r"(a3), "r"(b0), "r"(b1));
}

// ============ tf32 mma.sync GEMM: Y[M][Nn] = X[M][256] @ W[Nn][256]^T + bias ============
// 128x128 tile / CTA, 256 threads (8 warps, 2Mx4N), BK=32 floats, double-buffered cp.async.
// smem tiles: 128 rows x 128B, XOR swizzle: 16B-chunk ^= (row & 7).
#define GEMM_TILE_B 16384                       // 128 * 128 bytes
#define GEMM_SMEM  (4 * GEMM_TILE_B)            // A0 B0 A1 B1

__device__ __forceinline__ void load_tile(const float* __restrict__ G, int row0,
                                          int k0, uint32_t s_tile, int tid) {
    #pragma unroll
    for (int i = 0; i < 4; i++) {
        int v = tid + i * 256;                   // 0..1023 float4 slots
        int r = v >> 3, c4 = v & 7;
        uint32_t dst = s_tile + (uint32_t)(r * 128 + ((c4 ^ (r & 7)) << 4));
        cp_async16(dst, G + (size_t)(row0 + r) * 256 + k0 + c4 * 4);
    }
}

__global__ __launch_bounds__(256) void gemm_tf32(
    const float* __restrict__ X, const float* __restrict__ W,
    const float* __restrict__ bias, float* __restrict__ Y, int Nn)
{
    extern __shared__ char dsm[];
    uint32_t sbase = smem_to_u32(dsm);

    int tid = threadIdx.x;
    int wid = tid >> 5, lane = tid & 31;
    int warp_m = wid & 1;                        // 0..1  (x64 rows)
    int warp_n = wid >> 1;                       // 0..3  (x32 cols)
    int m0 = blockIdx.y * 128;
    int n0 = blockIdx.x * 128;

    // per-lane ldmatrix addressing precompute
    // A frag (mf): rows m = warp_m*64 + mf*16 + (lane&7) + ((lane>>3)&1)*8
    //              chunk = 2*ks + (lane>>4)
    int a_row = warp_m * 64 + (lane & 7) + ((lane >> 3) & 1) * 8;
    int a_hi = lane >> 4;                        // 0..1
    // B frag pair (p): rows n = warp_n*32 + p*16 + ((lane>>4)&1)*8 + (lane&7)
    //              chunk = 2*ks + ((lane>>3)&1)
    int b_row = warp_n * 32 + ((lane >> 4) & 1) * 8 + (lane & 7);
    int b_hi = (lane >> 3) & 1;

    float acc[4][4][4];
    #pragma unroll
    for (int i = 0; i < 4; i++)
        #pragma unroll
        for (int j = 0; j < 4; j++)
            #pragma unroll
            for (int t = 0; t < 4; t++) acc[i][j][t] = 0.0f;

    // prologue: chunk 0 -> buffer 0
    load_tile(X, m0, 0, sbase, tid);
    load_tile(W, n0, 0, sbase + GEMM_TILE_B, tid);
    CP_COMMIT();

    #pragma unroll 1
    for (int c = 0; c < 8; c++) {
        if (c < 7) {
            uint32_t buf = sbase + (uint32_t)(((c + 1) & 1) * 2 * GEMM_TILE_B);
            load_tile(X, m0, (c + 1) * 32, buf, tid);
            load_tile(W, n0, (c + 1) * 32, buf + GEMM_TILE_B, tid);
            CP_COMMIT();
            CP_WAIT(1);
        } else {
            CP_WAIT(0);
        }
        __syncthreads();

        uint32_t sA = sbase + (uint32_t)((c & 1) * 2 * GEMM_TILE_B);
        uint32_t sB = sA + GEMM_TILE_B;

        #pragma unroll
        for (int ks = 0; ks < 4; ks++) {
            uint32_t a[4][4], b[2][4];
            #pragma unroll
            for (int mf = 0; mf < 4; mf++) {
                int m = a_row + mf * 16;
                uint32_t addr = sA + (uint32_t)(m * 128
                              + (((2 * ks + a_hi) ^ (m & 7)) << 4));
                ldsm4(a[mf][0], a[mf][1], a[mf][2], a[mf][3], addr);
            }
            #pragma unroll
            for (int p = 0; p < 2; p++) {
                int n = b_row + p * 16;
                uint32_t addr = sB + (uint32_t)(n * 128
                              + (((2 * ks + b_hi) ^ (n & 7)) << 4));
                ldsm4(b[p][0], b[p][1], b[p][2], b[p][3], addr);
            }
            #pragma unroll
            for (int mf = 0; mf < 4; mf++)
                #pragma unroll
                for (int t = 0; t < 4; t++) a[mf][t] = to_tf32(a[mf][t]);
            #pragma unroll
            for (int p = 0; p < 2; p++)
                #pragma unroll
                for (int t = 0; t < 4; t++) b[p][t] = to_tf32(b[p][t]);

            #pragma unroll
            for (int mf = 0; mf < 4; mf++)
                #pragma unroll
                for (int nf = 0; nf < 4; nf++)
                    mma_tf32(acc[mf][nf][0], acc[mf][nf][1],
                             acc[mf][nf][2], acc[mf][nf][3],
                             a[mf][0], a[mf][1], a[mf][2], a[mf][3],
                             b[nf >> 1][(nf & 1) * 2], b[nf >> 1][(nf & 1) * 2 + 1]);
        }
        __syncthreads();
    }

    // epilogue: c0:(r, 2c) c1:(r, 2c+1) c2:(r+8, 2c) c3:(r+8, 2c+1)
    int er = lane >> 2, ec = (lane & 3) * 2;
    #pragma unroll
    for (int mf = 0; mf < 4; mf++) {
        int row = m0 + warp_m * 64 + mf * 16 + er;
        #pragma unroll
        for (int nf = 0; nf < 4; nf++) {
            int col = n0 + warp_n * 32 + nf * 8 + ec;
            float2 bv = *(const float2*)&bias[col];
            float2 o0, o1;
            o0.x = acc[mf][nf][0] + bv.x;
            o0.y = acc[mf][nf][1] + bv.y;
            o1.x = acc[mf][nf][2] + bv.x;
            o1.y = acc[mf][nf][3] + bv.y;
            *(float2*)&Y[(size_t)row * Nn + col] = o0;
            *(float2*)&Y[(size_t)(row + 8) * Nn + col] = o1;
        }
    }
}

// ---------------- gate kernel: g[blk][q][k][h], masked --------------------
__global__ __launch_bounds__(256) void gate_kernel(
    const float* __restrict__ mask_g, const float* __restrict__ ef,
    const float* __restrict__ w1, const float* __restrict__ b1,
    const float* __restrict__ w2, const float* __restrict__ b2)
{
    __shared__ float sm[64 * 64];
    __shared__ float sw1[64], sb1[16], sw2[128], sb2[8];
    int blk = blockIdx.x;
    int tid = threadIdx.x;

    const float* mbase = mask_g + (size_t)blk * 4096;
    #pragma unroll
    for (int i = 0; i < 16; i++) sm[tid + i * 256] = mbase[tid + i * 256];
    if (tid < 64)  sw1[tid] = w1[tid];
    if (tid < 16)  sb1[tid] = b1[tid];
    if (tid < 128) sw2[tid] = w2[tid];
    if (tid < 8)   sb2[tid] = b2[tid];
    __syncthreads();

    if (tid < 64) {                                  // diagonal fix-up
        float s = 0.0f;
        for (int k = 0; k < 64; k++) s += sm[tid * 64 + k];
        if (s < 1.0f) sm[tid * 64 + tid] = 1.0f;
    }
    __syncthreads();

    for (int it = 0; it < 16; it++) {
        int idx = tid + it * 256;                    // 0..4095
        int q = idx >> 6, k = idx & 63;
        float m = sm[idx];
        float out[8];
        if (m == 0.0f) {
            #pragma unroll
            for (int h = 0; h < 8; h++) out[h] = 0.0f;
        } else {
            float e0, e1, e2, e3;
            if (q == k) { e0 = e1 = e2 = 0.0f; e3 = 1.0f; }
            else {
                float4 ev = *(const float4*)(ef + ((size_t)blk * 4096 + idx) * 4);
                e0 = ev.x; e1 = ev.y; e2 = ev.z; e3 = ev.w;
            }
            float hh[16];
            #pragma unroll
            for (int j = 0; j < 16; j++) {
                float t = sb1[j] + sw1[j * 4] * e0 + sw1[j * 4 + 1] * e1
                        + sw1[j * 4 + 2] * e2 + sw1[j * 4 + 3] * e3;
                hh[j] = 0.5f * t * (1.0f + erff(t * 0.70710678118654752f));
            }
            #pragma unroll
            for (int h = 0; h < 8; h++) {
                float s = sb2[h];
                #pragma unroll
                for (int j = 0; j < 16; j++) s += sw2[h * 16 + j] * hh[j];
                out[h] = s;
            }
        }
        float* gp = g_gate + ((size_t)blk * 4096 + idx) * 8;
        *(float4*)(gp)     = make_float4(out[0], out[1], out[2], out[3]);
        *(float4*)(gp + 4) = make_float4(out[4], out[5], out[6], out[7]);
    }
}

// ---------------- attention kernel: one CTA per (b, block) ----------------
// dyn smem: Ks[64*256] Vs[64*256] Sb[64*65] Sc[64*65]  = 164352 bytes
#define ATTN_SMEM ((64 * 256 * 2 + 64 * 65 * 2) * 4)

__global__ __launch_bounds__(256) void attn_kernel(
    const float* __restrict__ mask_g, const float* __restrict__ ef)
{
    extern __shared__ float smem[];
    float* Ks = smem;
    float* Vs = Ks + 64 * 256;
    float* Sb = Vs + 64 * 256;     // bias-or-(-1e30) per (q,k), stride 65
    float* Sc = Sb + 64 * 65;      // scores / probs, stride 65

    int blk = blockIdx.x;
    int tid = threadIdx.x;
    int t0 = blk * 64;

    // stage K, V
    #pragma unroll
    for (int i = 0; i < 16; i++) {
        int v = tid + i * 256;               // float4 index, 0..4095
        int l = v >> 6, c4 = (v & 63) * 4;
        const float* base = g_qkv + (size_t)(t0 + l) * 768;
        *(float4*)&Ks[l * 256 + c4] = *(const float4*)(base + 256 + c4);
        *(float4*)&Vs[l * 256 + c4] = *(const float4*)(base + 512 + c4);
    }
    // stage mask into Sb
    #pragma unroll
    for (int i = 0; i < 16; i++) {
        int idx = tid + i * 256;
        Sb[(idx >> 6) * 65 + (idx & 63)] = mask_g[(size_t)blk * 4096 + idx];
    }
    __syncthreads();
    if (tid < 64) {                          // diagonal fix-up
        float s = 0.0f;
        for (int k = 0; k < 64; k++) s += Sb[tid * 65 + k];
        if (s < 1.0f) Sb[tid * 65 + tid] = 1.0f;
    }
    __syncthreads();
    // fold mask + physics bias into Sb
    #pragma unroll
    for (int i = 0; i < 16; i++) {
        int idx = tid + i * 256;
        int q = idx >> 6, k = idx & 63;
        float m = Sb[q * 65 + k];
        float bias = (q == k) ? 1.0f : ef[((size_t)blk * 4096 + idx) * 4 + 3];
        Sb[q * 65 + k] = (m == 0.0f) ? -1e30f : bias;
    }

    const float scale = 0.17677669529663687f;   // 32^-0.5

    for (int h = 0; h < 8; h++) {
        // ---- scores: thread handles (q = tid&63, 16 k's) ----
        int q = tid & 63;
        int kb = (tid >> 6) << 4;
        float4 qr[8];
        {
            const float* qg = g_qkv + (size_t)(t0 + q) * 768 + h * 32;
            #pragma unroll
            for (int d = 0; d < 8; d++) qr[d] = *(const float4*)(qg + d * 4);
        }
        __syncthreads();   // prev PV done reading Sc; Sb ready on first iter
        #pragma unroll 4
        for (int kk = 0; kk < 16; kk++) {
            int k = kb + kk;
            const float4* kr = (const float4*)&Ks[k * 256 + h * 32];
            float acc = 0.0f;
            #pragma unroll
            for (int d = 0; d < 8; d++) {
                float4 kv = kr[d];
                acc += qr[d].x * kv.x + qr[d].y * kv.y
                     + qr[d].z * kv.z + qr[d].w * kv.w;
            }
            Sc[q * 65 + k] = acc * scale + Sb[q * 65 + k];
        }
        __syncthreads();

        // ---- softmax + gate add: 4 lanes per row ----
        {
            int qq = tid >> 2, quad = tid & 3;
            float vals[16];
            float vmax = -3.0e38f;
            #pragma unroll
            for (int i = 0; i < 16; i++) {
                vals[i] = Sc[qq * 65 + quad * 16 + i];
                vmax = fmaxf(vmax, vals[i]);
            }
            vmax = fmaxf(vmax, __shfl_xor_sync(0xffffffffu, vmax, 1));
            vmax = fmaxf(vmax, __shfl_xor_sync(0xffffffffu, vmax, 2));
            float ssum = 0.0f;
            #pragma unroll
            for (int i = 0; i < 16; i++) {
                float e = __expf(vals[i] - vmax);
                vals[i] = e;
                ssum += e;
            }
            ssum += __shfl_xor_sync(0xffffffffu, ssum, 1);
            ssum += __shfl_xor_sync(0xffffffffu, ssum, 2);
            float inv = 1.0f / ssum;
            const float* gb = g_gate + ((size_t)blk * 4096 + qq * 64) * 8 + h;
            #pragma unroll
            for (int i = 0; i < 16; i++) {
                int k = quad * 16 + i;
                Sc[qq * 65 + k] = vals[i] * inv + gb[k * 8];
            }
        }
        __syncthreads();

        // ---- PV: thread handles (q = tid&63, 8 d's) ----
        {
            int dc = (tid >> 6) << 3;
            float acc[8];
            #pragma unroll
            for (int j = 0; j < 8; j++) acc[j] = 0.0f;
            #pragma unroll 4
            for (int k = 0; k < 64; k++) {
                float p = Sc[q * 65 + k];
                const float4* vr = (const float4*)&Vs[k * 256 + h * 32 + dc];
                float4 v0 = vr[0], v1 = vr[1];
                acc[0] += p * v0.x; acc[1] += p * v0.y;
                acc[2] += p * v0.z; acc[3] += p * v0.w;
                acc[4] += p * v1.x; acc[5] += p * v1.y;
                acc[6] += p * v1.z; acc[7] += p * v1.w;
            }
            float* og = g_xm + (size_t)(t0 + q) * 256 + h * 32 + dc;
            *(float4*)(og)     = make_float4(acc[0], acc[1], acc[2], acc[3]);
            *(float4*)(og + 4) = make_float4(acc[4], acc[5], acc[6], acc[7]);
        }
    }
}

// ---------------- launch ----------------
extern "C" void kernel_launch(void* const* d_in, const int* in_sizes, int n_in,
                              void* d_out, int out_size)
{
    const float* x      = (const float*)d_in[0];
    const float* amask  = (const float*)d_in[1];
    const float* efeat  = (const float*)d_in[2];
    const float* qkv_w  = (const float*)d_in[3];
    const float* qkv_b  = (const float*)d_in[4];
    const float* proj_w = (const float*)d_in[5];
    const float* proj_b = (const float*)d_in[6];
    const float* eg_w1  = (const float*)d_in[7];
    const float* eg_b1  = (const float*)d_in[8];
    const float* eg_w2  = (const float*)d_in[9];
    const float* eg_b2  = (const float*)d_in[10];
    float* out = (float*)d_out;

    void* p_qkv = nullptr;
    void* p_xm  = nullptr;
    cudaGetSymbolAddress(&p_qkv, g_qkv);
    cudaGetSymbolAddress(&p_xm, g_xm);

    cudaFuncSetAttribute(attn_kernel,
                         cudaFuncAttributeMaxDynamicSharedMemorySize, ATTN_SMEM);
    cudaFuncSetAttribute(gemm_tf32,
                         cudaFuncAttributeMaxDynamicSharedMemorySize, GEMM_SMEM);

    // 1) QKV projection: [32768,768] = x[32768,256] @ qkv_w^T  (tf32 mma.sync)
    gemm_tf32<<<dim3(768 / 128, NTOK / 128), 256, GEMM_SMEM>>>(
        x, qkv_w, qkv_b, (float*)p_qkv, 768);

    // 2) edge gate (independent of qkv)
    gate_kernel<<<NBLK, 256>>>(amask, efeat, eg_w1, eg_b1, eg_w2, eg_b2);

    // 3) block attention
    attn_kernel<<<NBLK, 256, ATTN_SMEM>>>(amask, efeat);

    // 4) output projection (tf32 mma.sync)
    gemm_tf32<<<dim3(CC / 128, NTOK / 128), 256, GEMM_SMEM>>>(
        (const float*)p_xm, proj_w, proj_b, out, CC);
}

// round 4
// speedup vs baseline: 1.9315x; 1.1750x over previous
#include <cuda_runtime.h>
#include <cuda_bf16.h>
#include <math.h>
#include <cstdint>

// Problem constants
#define BB    4
#define NTOK  32768          // B*N
#define CC    256
#define HH    8
#define HD    32
#define LL    64
#define NBLK  512            // B * NB
#define EGH   16

// ---------------- scratch (device globals; no allocs allowed) ----------------
__device__ float g_qkv[(size_t)NTOK * 768];          // [token][0:256 q | 256:512 k | 512:768 v]
__device__ float g_gate[(size_t)NBLK * 64 * 64 * 8]; // [blk][q][k][h]
__device__ float g_xm[(size_t)NTOK * CC];            // attention output

// ======================= PTX helpers (sm_80-compatible) =======================
__device__ __forceinline__ uint32_t smem_to_u32(const void* p) {
    uint32_t a;
    asm("{ .reg .u64 t; cvta.to.shared.u64 t, %1; cvt.u32.u64 %0, t; }"
        : "=r"(a) : "l"(p));
    return a;
}

__device__ __forceinline__ void cp_async16(uint32_t smem_addr, const void* gptr) {
    asm volatile("cp.async.cg.shared.global [%0], [%1], 16;"
                 :: "r"(smem_addr), "l"(gptr));
}
#define CP_COMMIT() asm volatile("cp.async.commit_group;" ::: "memory")
#define CP_WAIT(n)  asm volatile("cp.async.wait_group %0;" :: "n"(n) : "memory")

__device__ __forceinline__ void ldsm4(uint32_t& r0, uint32_t& r1, uint32_t& r2,
                                      uint32_t& r3, uint32_t addr) {
    asm volatile("ldmatrix.sync.aligned.m8n8.x4.shared.b16 {%0,%1,%2,%3}, [%4];"
                 : "=r"(r0), "=r"(r1), "=r"(r2), "=r"(r3) : "r"(addr));
}

__device__ __forceinline__ uint32_t to_tf32(uint32_t x) {
    uint32_t y;
    asm("cvt.rna.tf32.f32 %0, %1;" : "=r"(y) : "r"(x));
    return y;
}

__device__ __forceinline__ void split_tf32(uint32_t x, uint32_t& hi, uint32_t& lo) {
    hi = to_tf32(x);
    float r = __uint_as_float(x) - __uint_as_float(hi);
    lo = to_tf32(__float_as_uint(r));
}

__device__ __forceinline__ void mma_tf32(float& c0, float& c1, float& c2, float& c3,
                                         uint32_t a0, uint32_t a1, uint32_t a2, uint32_t a3,
                                         uint32_t b0, uint32_t b1) {
    asm volatile(
        "mma.sync.aligned.m16n8k8.row.col.f32.tf32.tf32.f32 "
        "{%0,%1,%2,%3}, {%4,%5,%6,%7}, {%8,%9}, {%0,%1,%2,%3};"
        : "+f"(c0), "+f"(c1), "+f"(c2), "+f"(c3)
        : "r"(a0), "r"(a1), "r"(a2), "r"(a3), "r"(b0), "r"(b1));
}

// ============ tf32 mma.sync GEMM: Y[M][Nn] = X[M][256] @ W[Nn][256]^T + bias ============
#define GEMM_TILE_B 16384                       // 128 * 128 bytes
#define GEMM_SMEM  (4 * GEMM_TILE_B)            // A0 B0 A1 B1

__device__ __forceinline__ void load_tile(const float* __restrict__ G, int row0,
                                          int k0, uint32_t s_tile, int tid) {
    #pragma unroll
    for (int i = 0; i < 4; i++) {
        int v = tid + i * 256;                   // 0..1023 float4 slots
        int r = v >> 3, c4 = v & 7;
        uint32_t dst = s_tile + (uint32_t)(r * 128 + ((c4 ^ (r & 7)) << 4));
        cp_async16(dst, G + (size_t)(row0 + r) * 256 + k0 + c4 * 4);
    }
}

__global__ __launch_bounds__(256) void gemm_tf32(
    const float* __restrict__ X, const float* __restrict__ W,
    const float* __restrict__ bias, float* __restrict__ Y, int Nn)
{
    extern __shared__ char dsm[];
    uint32_t sbase = smem_to_u32(dsm);

    int tid = threadIdx.x;
    int wid = tid >> 5, lane = tid & 31;
    int warp_m = wid & 1;
    int warp_n = wid >> 1;
    int m0 = blockIdx.y * 128;
    int n0 = blockIdx.x * 128;

    int a_row = warp_m * 64 + (lane & 7) + ((lane >> 3) & 1) * 8;
    int a_hi = lane >> 4;
    int b_row = warp_n * 32 + ((lane >> 4) & 1) * 8 + (lane & 7);
    int b_hi = (lane >> 3) & 1;

    float acc[4][4][4];
    #pragma unroll
    for (int i = 0; i < 4; i++)
        #pragma unroll
        for (int j = 0; j < 4; j++)
            #pragma unroll
            for (int t = 0; t < 4; t++) acc[i][j][t] = 0.0f;

    load_tile(X, m0, 0, sbase, tid);
    load_tile(W, n0, 0, sbase + GEMM_TILE_B, tid);
    CP_COMMIT();

    #pragma unroll 1
    for (int c = 0; c < 8; c++) {
        if (c < 7) {
            uint32_t buf = sbase + (uint32_t)(((c + 1) & 1) * 2 * GEMM_TILE_B);
            load_tile(X, m0, (c + 1) * 32, buf, tid);
            load_tile(W, n0, (c + 1) * 32, buf + GEMM_TILE_B, tid);
            CP_COMMIT();
            CP_WAIT(1);
        } else {
            CP_WAIT(0);
        }
        __syncthreads();

        uint32_t sA = sbase + (uint32_t)((c & 1) * 2 * GEMM_TILE_B);
        uint32_t sB = sA + GEMM_TILE_B;

        #pragma unroll
        for (int ks = 0; ks < 4; ks++) {
            uint32_t a[4][4], b[2][4];
            #pragma unroll
            for (int mf = 0; mf < 4; mf++) {
                int m = a_row + mf * 16;
                uint32_t addr = sA + (uint32_t)(m * 128
                              + (((2 * ks + a_hi) ^ (m & 7)) << 4));
                ldsm4(a[mf][0], a[mf][1], a[mf][2], a[mf][3], addr);
            }
            #pragma unroll
            for (int p = 0; p < 2; p++) {
                int n = b_row + p * 16;
                uint32_t addr = sB + (uint32_t)(n * 128
                              + (((2 * ks + b_hi) ^ (n & 7)) << 4));
                ldsm4(b[p][0], b[p][1], b[p][2], b[p][3], addr);
            }
            #pragma unroll
            for (int mf = 0; mf < 4; mf++)
                #pragma unroll
                for (int t = 0; t < 4; t++) a[mf][t] = to_tf32(a[mf][t]);
            #pragma unroll
            for (int p = 0; p < 2; p++)
                #pragma unroll
                for (int t = 0; t < 4; t++) b[p][t] = to_tf32(b[p][t]);

            #pragma unroll
            for (int mf = 0; mf < 4; mf++)
                #pragma unroll
                for (int nf = 0; nf < 4; nf++)
                    mma_tf32(acc[mf][nf][0], acc[mf][nf][1],
                             acc[mf][nf][2], acc[mf][nf][3],
                             a[mf][0], a[mf][1], a[mf][2], a[mf][3],
                             b[nf >> 1][(nf & 1) * 2], b[nf >> 1][(nf & 1) * 2 + 1]);
        }
        __syncthreads();
    }

    int er = lane >> 2, ec = (lane & 3) * 2;
    #pragma unroll
    for (int mf = 0; mf < 4; mf++) {
        int row = m0 + warp_m * 64 + mf * 16 + er;
        #pragma unroll
        for (int nf = 0; nf < 4; nf++) {
            int col = n0 + warp_n * 32 + nf * 8 + ec;
            float2 bv = *(const float2*)&bias[col];
            float2 o0, o1;
            o0.x = acc[mf][nf][0] + bv.x;
            o0.y = acc[mf][nf][1] + bv.y;
            o1.x = acc[mf][nf][2] + bv.x;
            o1.y = acc[mf][nf][3] + bv.y;
            *(float2*)&Y[(size_t)row * Nn + col] = o0;
            *(float2*)&Y[(size_t)(row + 8) * Nn + col] = o1;
        }
    }
}

// ---------------- gate kernel: g[blk][q][k][h], masked --------------------
__global__ __launch_bounds__(256) void gate_kernel(
    const float* __restrict__ mask_g, const float* __restrict__ ef,
    const float* __restrict__ w1, const float* __restrict__ b1,
    const float* __restrict__ w2, const float* __restrict__ b2)
{
    __shared__ float sm[64 * 64];
    __shared__ float sw1[64], sb1[16], sw2[128], sb2[8];
    int blk = blockIdx.x;
    int tid = threadIdx.x;

    const float* mbase = mask_g + (size_t)blk * 4096;
    #pragma unroll
    for (int i = 0; i < 16; i++) sm[tid + i * 256] = mbase[tid + i * 256];
    if (tid < 64)  sw1[tid] = w1[tid];
    if (tid < 16)  sb1[tid] = b1[tid];
    if (tid < 128) sw2[tid] = w2[tid];
    if (tid < 8)   sb2[tid] = b2[tid];
    __syncthreads();

    if (tid < 64) {
        float s = 0.0f;
        for (int k = 0; k < 64; k++) s += sm[tid * 64 + k];
        if (s < 1.0f) sm[tid * 64 + tid] = 1.0f;
    }
    __syncthreads();

    for (int it = 0; it < 16; it++) {
        int idx = tid + it * 256;
        int q = idx >> 6, k = idx & 63;
        float m = sm[idx];
        float out[8];
        if (m == 0.0f) {
            #pragma unroll
            for (int h = 0; h < 8; h++) out[h] = 0.0f;
        } else {
            float e0, e1, e2, e3;
            if (q == k) { e0 = e1 = e2 = 0.0f; e3 = 1.0f; }
            else {
                float4 ev = *(const float4*)(ef + ((size_t)blk * 4096 + idx) * 4);
                e0 = ev.x; e1 = ev.y; e2 = ev.z; e3 = ev.w;
            }
            float hh[16];
            #pragma unroll
            for (int j = 0; j < 16; j++) {
                float t = sb1[j] + sw1[j * 4] * e0 + sw1[j * 4 + 1] * e1
                        + sw1[j * 4 + 2] * e2 + sw1[j * 4 + 3] * e3;
                hh[j] = 0.5f * t * (1.0f + erff(t * 0.70710678118654752f));
            }
            #pragma unroll
            for (int h = 0; h < 8; h++) {
                float s = sb2[h];
                #pragma unroll
                for (int j = 0; j < 16; j++) s += sw2[h * 16 + j] * hh[j];
                out[h] = s;
            }
        }
        float* gp = g_gate + ((size_t)blk * 4096 + idx) * 8;
        *(float4*)(gp)     = make_float4(out[0], out[1], out[2], out[3]);
        *(float4*)(gp + 4) = make_float4(out[4], out[5], out[6], out[7]);
    }
}

// ---------------- attention kernel (tensor-core 3xTF32) --------------------
// One CTA per block of 64 tokens. 8 warps: 2 heads concurrently (4 warps each),
// 4 head-pair iterations.
// smem layout (floats):
#define SB_OFF   0                 // [64][66]  bias or -1e30
#define SC_OFF   4224              // [2][64][68] scores/probs
#define QH_OFF   12928             // [2][64][36]
#define KH_OFF   17536             // [2][64][36]
#define VT_OFF   22144             // [2][32][68] V transposed
#define ATTN_FLOATS 26496
#define ATTN_SMEM (ATTN_FLOATS * 4)

__global__ __launch_bounds__(256) void attn_mma(
    const float* __restrict__ mask_g, const float* __restrict__ ef)
{
    extern __shared__ float smf[];
    uint32_t sbase = smem_to_u32(smf);

    int blk = blockIdx.x;
    int tid = threadIdx.x;
    int wid = tid >> 5, lane = tid & 31;
    int half = wid >> 2;            // which head of the pair
    int wg = wid & 3;               // warp within 4-warp group
    int t0 = blk * 64;

    // ---- mask -> Sb (stride 66), diag fixup, fold bias ----
    #pragma unroll
    for (int i = 0; i < 16; i++) {
        int idx = tid + i * 256;
        smf[SB_OFF + (idx >> 6) * 66 + (idx & 63)] = mask_g[(size_t)blk * 4096 + idx];
    }
    __syncthreads();
    if (tid < 64) {
        float s = 0.0f;
        for (int k = 0; k < 64; k++) s += smf[SB_OFF + tid * 66 + k];
        if (s < 1.0f) smf[SB_OFF + tid * 66 + tid] = 1.0f;
    }
    __syncthreads();
    #pragma unroll
    for (int i = 0; i < 16; i++) {
        int idx = tid + i * 256;
        int q = idx >> 6, k = idx & 63;
        float m = smf[SB_OFF + q * 66 + k];
        float bias = (q == k) ? 1.0f : ef[((size_t)blk * 4096 + idx) * 4 + 3];
        smf[SB_OFF + q * 66 + k] = (m == 0.0f) ? -1e30f : bias;
    }

    const float scale = 0.17677669529663687f;   // 32^-0.5

    // frag addressing (byte offsets within padded tiles)
    int a7 = (lane & 7) + ((lane >> 3) & 1) * 8;     // A row pattern within 16
    int ahi16 = (lane >> 4) * 16;                    // A k-chunk byte sel
    int b7 = (lane & 7) + ((lane >> 4) & 1) * 8;     // B row pattern within 16
    int bhi16 = ((lane >> 3) & 1) * 16;              // B k-chunk byte sel
    int er = lane >> 2, ec = (lane & 3) * 2;

    #pragma unroll 1
    for (int it = 0; it < 4; it++) {
        __syncthreads();           // prev iter PV reads done; smem reusable

        // ---- stage Q, K (stride 36) and V^T (stride 68) for heads 2it, 2it+1 ----
        #pragma unroll
        for (int j = 0; j < 4; j++) {
            int idx = tid + j * 256;         // 0..1023
            int sh = idx >> 9;               // 0/1
            int rem = idx & 511;
            int t = rem >> 3, c4 = rem & 7;
            int head = it * 2 + sh;
            const float* src = g_qkv + (size_t)(t0 + t) * 768 + head * 32 + c4 * 4;
            float4 qv = *(const float4*)(src);
            float4 kv = *(const float4*)(src + 256);
            float4 vv = *(const float4*)(src + 512);
            *(float4*)&smf[QH_OFF + sh * 2304 + t * 36 + c4 * 4] = qv;
            *(float4*)&smf[KH_OFF + sh * 2304 + t * 36 + c4 * 4] = kv;
            float* vt = &smf[VT_OFF + sh * 2176 + c4 * 4 * 68 + t];
            vt[0]      = vv.x;
            vt[68]     = vv.y;
            vt[136]    = vv.z;
            vt[204]    = vv.w;
        }
        __syncthreads();

        int head = it * 2 + half;

        // ---- QK^T (3xTF32): warp computes rows [wg*16,+16) x all 64 cols ----
        {
            uint32_t sQ = sbase + (QH_OFF + half * 2304) * 4;
            uint32_t sK = sbase + (KH_OFF + half * 2304) * 4;
            uint32_t aAddr = sQ + (uint32_t)((wg * 16 + a7) * 144 + ahi16);
            uint32_t bAddr = sK + (uint32_t)(b7 * 144 + bhi16);

            float acc[8][4];
            #pragma unroll
            for (int nt = 0; nt < 8; nt++)
                #pragma unroll
                for (int t = 0; t < 4; t++) acc[nt][t] = 0.0f;

            #pragma unroll
            for (int ks = 0; ks < 4; ks++) {
                uint32_t a[4], ah[4], al[4];
                ldsm4(a[0], a[1], a[2], a[3], aAddr + ks * 32);
                #pragma unroll
                for (int t = 0; t < 4; t++) split_tf32(a[t], ah[t], al[t]);
                uint32_t bh[4][4], bl[4][4];
                #pragma unroll
                for (int p = 0; p < 4; p++) {
                    uint32_t b[4];
                    ldsm4(b[0], b[1], b[2], b[3],
                          bAddr + (uint32_t)(p * 16 * 144) + ks * 32);
                    #pragma unroll
                    for (int t = 0; t < 4; t++) split_tf32(b[t], bh[p][t], bl[p][t]);
                }
                #pragma unroll
                for (int nt = 0; nt < 8; nt++) {
                    int p = nt >> 1, i0 = (nt & 1) * 2;
                    mma_tf32(acc[nt][0], acc[nt][1], acc[nt][2], acc[nt][3],
                             ah[0], ah[1], ah[2], ah[3], bh[p][i0], bh[p][i0 + 1]);
                    mma_tf32(acc[nt][0], acc[nt][1], acc[nt][2], acc[nt][3],
                             ah[0], ah[1], ah[2], ah[3], bl[p][i0], bl[p][i0 + 1]);
                    mma_tf32(acc[nt][0], acc[nt][1], acc[nt][2], acc[nt][3],
                             al[0], al[1], al[2], al[3], bh[p][i0], bh[p][i0 + 1]);
                }
            }

            // epilogue: Sc = acc*scale + Sb
            float* Scm = &smf[SC_OFF + half * 4352];
            int row = wg * 16 + er;
            #pragma unroll
            for (int nt = 0; nt < 8; nt++) {
                int col = nt * 8 + ec;
                float2 s0 = *(float2*)&smf[SB_OFF + row * 66 + col];
                float2 s1 = *(float2*)&smf[SB_OFF + (row + 8) * 66 + col];
                float2 o0, o1;
                o0.x = acc[nt][0] * scale + s0.x;
                o0.y = acc[nt][1] * scale + s0.y;
                o1.x = acc[nt][2] * scale + s1.x;
                o1.y = acc[nt][3] * scale + s1.y;
                *(float2*)&Scm[row * 68 + col] = o0;
                *(float2*)&Scm[(row + 8) * 68 + col] = o1;
            }
        }
        __syncthreads();

        // ---- softmax + gate (all 256 threads per matrix, 2 matrices) ----
        #pragma unroll 1
        for (int sh = 0; sh < 2; sh++) {
            float* Scm = &smf[SC_OFF + sh * 4352];
            int hh2 = it * 2 + sh;
            int qq = tid >> 2, quad = tid & 3;
            float vals[16];
            float vmax = -3.0e38f;
            #pragma unroll
            for (int i = 0; i < 16; i++) {
                vals[i] = Scm[qq * 68 + quad * 16 + i];
                vmax = fmaxf(vmax, vals[i]);
            }
            vmax = fmaxf(vmax, __shfl_xor_sync(0xffffffffu, vmax, 1));
            vmax = fmaxf(vmax, __shfl_xor_sync(0xffffffffu, vmax, 2));
            float ssum = 0.0f;
            #pragma unroll
            for (int i = 0; i < 16; i++) {
                float e = __expf(vals[i] - vmax);
                vals[i] = e;
                ssum += e;
            }
            ssum += __shfl_xor_sync(0xffffffffu, ssum, 1);
            ssum += __shfl_xor_sync(0xffffffffu, ssum, 2);
            float inv = 1.0f / ssum;
            const float* gb = g_gate + ((size_t)blk * 4096 + qq * 64) * 8 + hh2;
            #pragma unroll
            for (int i = 0; i < 16; i++) {
                int k = quad * 16 + i;
                Scm[qq * 68 + k] = vals[i] * inv + gb[k * 8];
            }
        }
        __syncthreads();

        // ---- PV (3xTF32): warp computes O rows [wg*16,+16) x 32 dims ----
        {
            uint32_t sP = sbase + (SC_OFF + half * 4352) * 4;
            uint32_t sV = sbase + (VT_OFF + half * 2176) * 4;
            uint32_t aAddr = sP + (uint32_t)((wg * 16 + a7) * 272 + ahi16);
            uint32_t bAddr = sV + (uint32_t)(b7 * 272 + bhi16);

            float acc[4][4];
            #pragma unroll
            for (int nt = 0; nt < 4; nt++)
                #pragma unroll
                for (int t = 0; t < 4; t++) acc[nt][t] = 0.0f;

            #pragma unroll
            for (int ks = 0; ks < 8; ks++) {
                uint32_t a[4], ah[4], al[4];
                ldsm4(a[0], a[1], a[2], a[3], aAddr + ks * 32);
                #pragma unroll
                for (int t = 0; t < 4; t++) split_tf32(a[t], ah[t], al[t]);
                uint32_t bh[2][4], bl[2][4];
                #pragma unroll
                for (int p = 0; p < 2; p++) {
                    uint32_t b[4];
                    ldsm4(b[0], b[1], b[2], b[3],
                          bAddr + (uint32_t)(p * 16 * 272) + ks * 32);
                    #pragma unroll
                    for (int t = 0; t < 4; t++) split_tf32(b[t], bh[p][t], bl[p][t]);
                }
                #pragma unroll
                for (int nt = 0; nt < 4; nt++) {
                    int p = nt >> 1, i0 = (nt & 1) * 2;
                    mma_tf32(acc[nt][0], acc[nt][1], acc[nt][2], acc[nt][3],
                             ah[0], ah[1], ah[2], ah[3], bh[p][i0], bh[p][i0 + 1]);
                    mma_tf32(acc[nt][0], acc[nt][1], acc[nt][2], acc[nt][3],
                             ah[0], ah[1], ah[2], ah[3], bl[p][i0], bl[p][i0 + 1]);
                    mma_tf32(acc[nt][0], acc[nt][1], acc[nt][2], acc[nt][3],
                             al[0], al[1], al[2], al[3], bh[p][i0], bh[p][i0 + 1]);
                }
            }

            int row = wg * 16 + er;
            float* og0 = g_xm + (size_t)(t0 + row) * 256 + head * 32;
            float* og1 = g_xm + (size_t)(t0 + row + 8) * 256 + head * 32;
            #pragma unroll
            for (int nt = 0; nt < 4; nt++) {
                int col = nt * 8 + ec;
                *(float2*)&og0[col] = make_float2(acc[nt][0], acc[nt][1]);
                *(float2*)&og1[col] = make_float2(acc[nt][2], acc[nt][3]);
            }
        }
    }
}

// ---------------- launch ----------------
extern "C" void kernel_launch(void* const* d_in, const int* in_sizes, int n_in,
                              void* d_out, int out_size)
{
    const float* x      = (const float*)d_in[0];
    const float* amask  = (const float*)d_in[1];
    const float* efeat  = (const float*)d_in[2];
    const float* qkv_w  = (const float*)d_in[3];
    const float* qkv_b  = (const float*)d_in[4];
    const float* proj_w = (const float*)d_in[5];
    const float* proj_b = (const float*)d_in[6];
    const float* eg_w1  = (const float*)d_in[7];
    const float* eg_b1  = (const float*)d_in[8];
    const float* eg_w2  = (const float*)d_in[9];
    const float* eg_b2  = (const float*)d_in[10];
    float* out = (float*)d_out;

    void* p_qkv = nullptr;
    void* p_xm  = nullptr;
    cudaGetSymbolAddress(&p_qkv, g_qkv);
    cudaGetSymbolAddress(&p_xm, g_xm);

    cudaFuncSetAttribute(attn_mma,
                         cudaFuncAttributeMaxDynamicSharedMemorySize, ATTN_SMEM);
    cudaFuncSetAttribute(gemm_tf32,
                         cudaFuncAttributeMaxDynamicSharedMemorySize, GEMM_SMEM);

    // 1) QKV projection (tf32 mma.sync)
    gemm_tf32<<<dim3(768 / 128, NTOK / 128), 256, GEMM_SMEM>>>(
        x, qkv_w, qkv_b, (float*)p_qkv, 768);

    // 2) edge gate
    gate_kernel<<<NBLK, 256>>>(amask, efeat, eg_w1, eg_b1, eg_w2, eg_b2);

    // 3) block attention (tensor cores, 3xTF32)
    attn_mma<<<NBLK, 256, ATTN_SMEM>>>(amask, efeat);

    // 4) output projection (tf32 mma.sync)
    gemm_tf32<<<dim3(CC / 128, NTOK / 128), 256, GEMM_SMEM>>>(
        (const float*)p_xm, proj_w, proj_b, out, CC);
}

// round 5
// speedup vs baseline: 2.3006x; 1.1911x over previous
#include <cuda_runtime.h>
#include <cuda_bf16.h>
#include <math.h>
#include <cstdint>

// Problem constants
#define BB    4
#define NTOK  32768          // B*N
#define CC    256
#define HH    8
#define HD    32
#define LL    64
#define NBLK  512            // B * NB
#define EGH   16

// ---------------- scratch (device globals; no allocs allowed) ----------------
__device__ float g_qkv[(size_t)NTOK * 768];          // [token][0:256 q | 256:512 k | 512:768 v]
__device__ float g_gate[(size_t)NBLK * 8 * 64 * 64]; // [blk][h][q][k]
__device__ float g_xm[(size_t)NTOK * CC];            // attention output

// ======================= PTX helpers (sm_80-compatible) =======================
__device__ __forceinline__ uint32_t smem_to_u32(const void* p) {
    uint32_t a;
    asm("{ .reg .u64 t; cvta.to.shared.u64 t, %1; cvt.u32.u64 %0, t; }"
        : "=r"(a) : "l"(p));
    return a;
}

__device__ __forceinline__ void ldsm4(uint32_t& r0, uint32_t& r1, uint32_t& r2,
                                      uint32_t& r3, uint32_t addr) {
    asm volatile("ldmatrix.sync.aligned.m8n8.x4.shared.b16 {%0,%1,%2,%3}, [%4];"
                 : "=r"(r0), "=r"(r1), "=r"(r2), "=r"(r3) : "r"(addr));
}

__device__ __forceinline__ uint32_t to_tf32(uint32_t x) {
    uint32_t y;
    asm("cvt.rna.tf32.f32 %0, %1;" : "=r"(y) : "r"(x));
    return y;
}

__device__ __forceinline__ float to_tf32f(float x) {
    return __uint_as_float(to_tf32(__float_as_uint(x)));
}

__device__ __forceinline__ void split_tf32(uint32_t x, uint32_t& hi, uint32_t& lo) {
    hi = to_tf32(x);
    float r = __uint_as_float(x) - __uint_as_float(hi);
    lo = to_tf32(__float_as_uint(r));
}

__device__ __forceinline__ void split4(float4 v, float4& hi, float4& lo) {
    hi.x = to_tf32f(v.x); lo.x = to_tf32f(v.x - hi.x);
    hi.y = to_tf32f(v.y); lo.y = to_tf32f(v.y - hi.y);
    hi.z = to_tf32f(v.z); lo.z = to_tf32f(v.z - hi.z);
    hi.w = to_tf32f(v.w); lo.w = to_tf32f(v.w - hi.w);
}

__device__ __forceinline__ void mma_tf32(float& c0, float& c1, float& c2, float& c3,
                                         uint32_t a0, uint32_t a1, uint32_t a2, uint32_t a3,
                                         uint32_t b0, uint32_t b1) {
    asm volatile(
        "mma.sync.aligned.m16n8k8.row.col.f32.tf32.tf32.f32 "
        "{%0,%1,%2,%3}, {%4,%5,%6,%7}, {%8,%9}, {%0,%1,%2,%3};"
        : "+f"(c0), "+f"(c1), "+f"(c2), "+f"(c3)
        : "r"(a0), "r"(a1), "r"(a2), "r"(a3), "r"(b0), "r"(b1));
}

// ============ tf32 mma.sync GEMM: Y[M][Nn] = X[M][256] @ W[Nn][256]^T + bias ============
// LDG-staged (pre-converted to tf32 at STS time); inner loop is pure ldmatrix+MMA.
#define GEMM_TILE_B 16384                       // 128 * 128 bytes
#define GEMM_SMEM  (4 * GEMM_TILE_B)            // A0 B0 A1 B1

__global__ __launch_bounds__(256) void gemm_tf32(
    const float* __restrict__ X, const float* __restrict__ W,
    const float* __restrict__ bias, float* __restrict__ Y, int Nn)
{
    extern __shared__ char dsm[];
    uint32_t sbase = smem_to_u32(dsm);

    int tid = threadIdx.x;
    int wid = tid >> 5, lane = tid & 31;
    int warp_m = wid & 1;
    int warp_n = wid >> 1;
    int m0 = blockIdx.y * 128;
    int n0 = blockIdx.x * 128;

    // staging addressing: thread handles rows r, r+32, r+64, r+96; 16B chunk c4
    int r = tid >> 3;                            // 0..31
    int c4 = tid & 7;
    uint32_t sc = (uint32_t)((c4 ^ (r & 7)) << 4);   // swizzled chunk byte offset
    const float* xg = X + (size_t)(m0 + r) * 256 + c4 * 4;
    const float* wg = W + (size_t)(n0 + r) * 256 + c4 * 4;

    int a_row = warp_m * 64 + (lane & 7) + ((lane >> 3) & 1) * 8;
    int a_hi = lane >> 4;
    int b_row = warp_n * 32 + ((lane >> 4) & 1) * 8 + (lane & 7);
    int b_hi = (lane >> 3) & 1;

    float acc[4][4][4];
    #pragma unroll
    for (int i = 0; i < 4; i++)
        #pragma unroll
        for (int j = 0; j < 4; j++)
            #pragma unroll
            for (int t = 0; t < 4; t++) acc[i][j][t] = 0.0f;

    float4 rx[4], rw[4];
    #pragma unroll
    for (int i = 0; i < 4; i++) {                // prologue: chunk 0 -> regs
        rx[i] = *(const float4*)(xg + i * 8192);
        rw[i] = *(const float4*)(wg + i * 8192);
    }
    // store chunk 0 (converted) into buffer 0
    {
        uint32_t bufA = sbase, bufB = sbase + GEMM_TILE_B;
        #pragma unroll
        for (int i = 0; i < 4; i++) {
            uint32_t d = (uint32_t)((r + i * 32) * 128) + sc;
            float4 cx, cw;
            cx.x = to_tf32f(rx[i].x); cx.y = to_tf32f(rx[i].y);
            cx.z = to_tf32f(rx[i].z); cx.w = to_tf32f(rx[i].w);
            cw.x = to_tf32f(rw[i].x); cw.y = to_tf32f(rw[i].y);
            cw.z = to_tf32f(rw[i].z); cw.w = to_tf32f(rw[i].w);
            *(float4*)(dsm + (bufA + d - sbase)) = cx;
            *(float4*)(dsm + (bufB + d - sbase)) = cw;
        }
    }
    __syncthreads();

    #pragma unroll 1
    for (int c = 0; c < 8; c++) {
        if (c < 7) {                              // issue next-chunk LDGs early
            #pragma unroll
            for (int i = 0; i < 4; i++) {
                rx[i] = *(const float4*)(xg + (c + 1) * 32 + i * 8192);
                rw[i] = *(const float4*)(wg + (c + 1) * 32 + i * 8192);
            }
        }

        uint32_t sA = sbase + (uint32_t)((c & 1) * 2 * GEMM_TILE_B);
        uint32_t sB = sA + GEMM_TILE_B;

        #pragma unroll
        for (int ks = 0; ks < 4; ks++) {
            uint32_t a[4][4], b[2][4];
            #pragma unroll
            for (int mf = 0; mf < 4; mf++) {
                int m = a_row + mf * 16;
                uint32_t addr = sA + (uint32_t)(m * 128
                              + (((2 * ks + a_hi) ^ (m & 7)) << 4));
                ldsm4(a[mf][0], a[mf][1], a[mf][2], a[mf][3], addr);
            }
            #pragma unroll
            for (int p = 0; p < 2; p++) {
                int n = b_row + p * 16;
                uint32_t addr = sB + (uint32_t)(n * 128
                              + (((2 * ks + b_hi) ^ (n & 7)) << 4));
                ldsm4(b[p][0], b[p][1], b[p][2], b[p][3], addr);
            }
            #pragma unroll
            for (int mf = 0; mf < 4; mf++)
                #pragma unroll
                for (int nf = 0; nf < 4; nf++)
                    mma_tf32(acc[mf][nf][0], acc[mf][nf][1],
                             acc[mf][nf][2], acc[mf][nf][3],
                             a[mf][0], a[mf][1], a[mf][2], a[mf][3],
                             b[nf >> 1][(nf & 1) * 2], b[nf >> 1][(nf & 1) * 2 + 1]);
        }
        __syncthreads();

        if (c < 7) {                              // convert + store next chunk
            uint32_t bufA = sbase + (uint32_t)(((c + 1) & 1) * 2 * GEMM_TILE_B);
            uint32_t bufB = bufA + GEMM_TILE_B;
            #pragma unroll
            for (int i = 0; i < 4; i++) {
                uint32_t d = (uint32_t)((r + i * 32) * 128) + sc;
                float4 cx, cw;
                cx.x = to_tf32f(rx[i].x); cx.y = to_tf32f(rx[i].y);
                cx.z = to_tf32f(rx[i].z); cx.w = to_tf32f(rx[i].w);
                cw.x = to_tf32f(rw[i].x); cw.y = to_tf32f(rw[i].y);
                cw.z = to_tf32f(rw[i].z); cw.w = to_tf32f(rw[i].w);
                *(float4*)(dsm + (bufA + d - sbase)) = cx;
                *(float4*)(dsm + (bufB + d - sbase)) = cw;
            }
            __syncthreads();
        }
    }

    int er = lane >> 2, ec = (lane & 3) * 2;
    #pragma unroll
    for (int mf = 0; mf < 4; mf++) {
        int row = m0 + warp_m * 64 + mf * 16 + er;
        #pragma unroll
        for (int nf = 0; nf < 4; nf++) {
            int col = n0 + warp_n * 32 + nf * 8 + ec;
            float2 bv = *(const float2*)&bias[col];
            float2 o0, o1;
            o0.x = acc[mf][nf][0] + bv.x;
            o0.y = acc[mf][nf][1] + bv.y;
            o1.x = acc[mf][nf][2] + bv.x;
            o1.y = acc[mf][nf][3] + bv.y;
            *(float2*)&Y[(size_t)row * Nn + col] = o0;
            *(float2*)&Y[(size_t)(row + 8) * Nn + col] = o1;
        }
    }
}

// ---------------- gate kernel: g[blk][h][q][k], masked --------------------
__global__ __launch_bounds__(256) void gate_kernel(
    const float* __restrict__ mask_g, const float* __restrict__ ef,
    const float* __restrict__ w1, const float* __restrict__ b1,
    const float* __restrict__ w2, const float* __restrict__ b2)
{
    __shared__ float sm[64 * 64];
    __shared__ float sw1[64], sb1[16], sw2[128], sb2[8];
    int blk = blockIdx.x;
    int tid = threadIdx.x;

    const float* mbase = mask_g + (size_t)blk * 4096;
    #pragma unroll
    for (int i = 0; i < 16; i++) sm[tid + i * 256] = mbase[tid + i * 256];
    if (tid < 64)  sw1[tid] = w1[tid];
    if (tid < 16)  sb1[tid] = b1[tid];
    if (tid < 128) sw2[tid] = w2[tid];
    if (tid < 8)   sb2[tid] = b2[tid];
    __syncthreads();

    if (tid < 64) {
        float s = 0.0f;
        for (int k = 0; k < 64; k++) s += sm[tid * 64 + k];
        if (s < 1.0f) sm[tid * 64 + tid] = 1.0f;
    }
    __syncthreads();

    for (int it = 0; it < 16; it++) {
        int idx = tid + it * 256;
        int q = idx >> 6, k = idx & 63;
        float m = sm[idx];
        float out[8];
        if (m == 0.0f) {
            #pragma unroll
            for (int h = 0; h < 8; h++) out[h] = 0.0f;
        } else {
            float e0, e1, e2, e3;
            if (q == k) { e0 = e1 = e2 = 0.0f; e3 = 1.0f; }
            else {
                float4 ev = *(const float4*)(ef + ((size_t)blk * 4096 + idx) * 4);
                e0 = ev.x; e1 = ev.y; e2 = ev.z; e3 = ev.w;
            }
            float hh[16];
            #pragma unroll
            for (int j = 0; j < 16; j++) {
                float t = sb1[j] + sw1[j * 4] * e0 + sw1[j * 4 + 1] * e1
                        + sw1[j * 4 + 2] * e2 + sw1[j * 4 + 3] * e3;
                hh[j] = 0.5f * t * (1.0f + erff(t * 0.70710678118654752f));
            }
            #pragma unroll
            for (int h = 0; h < 8; h++) {
                float s = sb2[h];
                #pragma unroll
                for (int j = 0; j < 16; j++) s += sw2[h * 16 + j] * hh[j];
                out[h] = s;
            }
        }
        float* gp = g_gate + (size_t)blk * 32768 + idx;
        #pragma unroll
        for (int h = 0; h < 8; h++) gp[h * 4096] = out[h];
    }
}

// ---------------- attention kernel (tensor-core 3xTF32) --------------------
// One CTA / 64-token block. 8 warps: 2 heads concurrently, 4 head-pair iters.
// K and V pre-split into tf32 hi/lo tiles at staging (B operands shared by 4 warps).
#define SB_OFF    0                 // [64][66]
#define SC_OFF    4224              // [2][64][68]
#define QH_OFF    12928             // [2][64][36]
#define KHI_OFF   17536             // [2][64][36]
#define KLO_OFF   22144             // [2][64][36]
#define VTHI_OFF  26752             // [2][32][68]
#define VTLO_OFF  31104             // [2][32][68]
#define ATTN_FLOATS 35456
#define ATTN_SMEM (ATTN_FLOATS * 4)

__global__ __launch_bounds__(256) void attn_mma(
    const float* __restrict__ mask_g, const float* __restrict__ ef)
{
    extern __shared__ float smf[];
    uint32_t sbase = smem_to_u32(smf);

    int blk = blockIdx.x;
    int tid = threadIdx.x;
    int wid = tid >> 5, lane = tid & 31;
    int half = wid >> 2;
    int wg = wid & 3;
    int t0 = blk * 64;

    // ---- mask -> Sb, diag fixup, fold bias ----
    #pragma unroll
    for (int i = 0; i < 16; i++) {
        int idx = tid + i * 256;
        smf[SB_OFF + (idx >> 6) * 66 + (idx & 63)] = mask_g[(size_t)blk * 4096 + idx];
    }
    __syncthreads();
    if (tid < 64) {
        float s = 0.0f;
        for (int k = 0; k < 64; k++) s += smf[SB_OFF + tid * 66 + k];
        if (s < 1.0f) smf[SB_OFF + tid * 66 + tid] = 1.0f;
    }
    __syncthreads();
    #pragma unroll
    for (int i = 0; i < 16; i++) {
        int idx = tid + i * 256;
        int q = idx >> 6, k = idx & 63;
        float m = smf[SB_OFF + q * 66 + k];
        float bias = (q == k) ? 1.0f : ef[((size_t)blk * 4096 + idx) * 4 + 3];
        smf[SB_OFF + q * 66 + k] = (m == 0.0f) ? -1e30f : bias;
    }

    const float scale = 0.17677669529663687f;

    int a7 = (lane & 7) + ((lane >> 3) & 1) * 8;
    int ahi16 = (lane >> 4) * 16;
    int b7 = (lane & 7) + ((lane >> 4) & 1) * 8;
    int bhi16 = ((lane >> 3) & 1) * 16;
    int er = lane >> 2, ec = (lane & 3) * 2;

    #pragma unroll 1
    for (int it = 0; it < 4; it++) {
        __syncthreads();

        // ---- stage Q (fp32) and pre-split K, V^T for heads 2it, 2it+1 ----
        #pragma unroll
        for (int j = 0; j < 4; j++) {
            int idx = tid + j * 256;
            int sh = idx >> 9;
            int rem = idx & 511;
            int t = rem >> 3, c4 = rem & 7;
            int head = it * 2 + sh;
            const float* src = g_qkv + (size_t)(t0 + t) * 768 + head * 32 + c4 * 4;
            float4 qv = *(const float4*)(src);
            float4 kv = *(const float4*)(src + 256);
            float4 vv = *(const float4*)(src + 512);
            *(float4*)&smf[QH_OFF + sh * 2304 + t * 36 + c4 * 4] = qv;
            float4 khi, klo; split4(kv, khi, klo);
            *(float4*)&smf[KHI_OFF + sh * 2304 + t * 36 + c4 * 4] = khi;
            *(float4*)&smf[KLO_OFF + sh * 2304 + t * 36 + c4 * 4] = klo;
            float4 vhi, vlo; split4(vv, vhi, vlo);
            float* vh = &smf[VTHI_OFF + sh * 2176 + (c4 * 4) * 68 + t];
            vh[0] = vhi.x; vh[68] = vhi.y; vh[136] = vhi.z; vh[204] = vhi.w;
            float* vl = &smf[VTLO_OFF + sh * 2176 + (c4 * 4) * 68 + t];
            vl[0] = vlo.x; vl[68] = vlo.y; vl[136] = vlo.z; vl[204] = vlo.w;
        }
        __syncthreads();

        int head = it * 2 + half;

        // ---- QK^T (3xTF32): warp computes rows [wg*16,+16) x 64 cols ----
        {
            uint32_t sQ = sbase + (QH_OFF + half * 2304) * 4;
            uint32_t sKh = sbase + (KHI_OFF + half * 2304) * 4;
            uint32_t sKl = sbase + (KLO_OFF + half * 2304) * 4;
            uint32_t aAddr = sQ + (uint32_t)((wg * 16 + a7) * 144 + ahi16);
            uint32_t bAddrH = sKh + (uint32_t)(b7 * 144 + bhi16);
            uint32_t bAddrL = sKl + (uint32_t)(b7 * 144 + bhi16);

            float acc[8][4];
            #pragma unroll
            for (int nt = 0; nt < 8; nt++)
                #pragma unroll
                for (int t = 0; t < 4; t++) acc[nt][t] = 0.0f;

            #pragma unroll
            for (int ks = 0; ks < 4; ks++) {
                uint32_t a[4], ah[4], al[4];
                ldsm4(a[0], a[1], a[2], a[3], aAddr + ks * 32);
                #pragma unroll
                for (int t = 0; t < 4; t++) split_tf32(a[t], ah[t], al[t]);
                uint32_t bh[4][4], bl[4][4];
                #pragma unroll
                for (int p = 0; p < 4; p++) {
                    ldsm4(bh[p][0], bh[p][1], bh[p][2], bh[p][3],
                          bAddrH + (uint32_t)(p * 16 * 144) + ks * 32);
                    ldsm4(bl[p][0], bl[p][1], bl[p][2], bl[p][3],
                          bAddrL + (uint32_t)(p * 16 * 144) + ks * 32);
                }
                #pragma unroll
                for (int nt = 0; nt < 8; nt++) {
                    int p = nt >> 1, i0 = (nt & 1) * 2;
                    mma_tf32(acc[nt][0], acc[nt][1], acc[nt][2], acc[nt][3],
                             ah[0], ah[1], ah[2], ah[3], bh[p][i0], bh[p][i0 + 1]);
                    mma_tf32(acc[nt][0], acc[nt][1], acc[nt][2], acc[nt][3],
                             ah[0], ah[1], ah[2], ah[3], bl[p][i0], bl[p][i0 + 1]);
                    mma_tf32(acc[nt][0], acc[nt][1], acc[nt][2], acc[nt][3],
                             al[0], al[1], al[2], al[3], bh[p][i0], bh[p][i0 + 1]);
                }
            }

            float* Scm = &smf[SC_OFF + half * 4352];
            int row = wg * 16 + er;
            #pragma unroll
            for (int nt = 0; nt < 8; nt++) {
                int col = nt * 8 + ec;
                float2 s0 = *(float2*)&smf[SB_OFF + row * 66 + col];
                float2 s1 = *(float2*)&smf[SB_OFF + (row + 8) * 66 + col];
                float2 o0, o1;
                o0.x = acc[nt][0] * scale + s0.x;
                o0.y = acc[nt][1] * scale + s0.y;
                o1.x = acc[nt][2] * scale + s1.x;
                o1.y = acc[nt][3] * scale + s1.y;
                *(float2*)&Scm[row * 68 + col] = o0;
                *(float2*)&Scm[(row + 8) * 68 + col] = o1;
            }
        }
        __syncthreads();

        // ---- softmax + gate add (coalesced gate reads) ----
        #pragma unroll 1
        for (int sh = 0; sh < 2; sh++) {
            float* Scm = &smf[SC_OFF + sh * 4352];
            int hh2 = it * 2 + sh;
            int qq = tid >> 2, quad = tid & 3;
            float vals[16];
            float vmax = -3.0e38f;
            #pragma unroll
            for (int i = 0; i < 16; i++) {
                vals[i] = Scm[qq * 68 + quad * 16 + i];
                vmax = fmaxf(vmax, vals[i]);
            }
            vmax = fmaxf(vmax, __shfl_xor_sync(0xffffffffu, vmax, 1));
            vmax = fmaxf(vmax, __shfl_xor_sync(0xffffffffu, vmax, 2));
            float ssum = 0.0f;
            #pragma unroll
            for (int i = 0; i < 16; i++) {
                float e = __expf(vals[i] - vmax);
                vals[i] = e;
                ssum += e;
            }
            ssum += __shfl_xor_sync(0xffffffffu, ssum, 1);
            ssum += __shfl_xor_sync(0xffffffffu, ssum, 2);
            float inv = 1.0f / ssum;
            const float* gb = g_gate + (size_t)blk * 32768 + (size_t)hh2 * 4096
                            + qq * 64 + quad * 16;
            float gv[16];
            #pragma unroll
            for (int i = 0; i < 4; i++)
                *(float4*)&gv[i * 4] = *(const float4*)&gb[i * 4];
            #pragma unroll
            for (int i = 0; i < 16; i++)
                Scm[qq * 68 + quad * 16 + i] = vals[i] * inv + gv[i];
        }
        __syncthreads();

        // ---- PV (3xTF32): warp computes O rows [wg*16,+16) x 32 dims ----
        {
            uint32_t sP = sbase + (SC_OFF + half * 4352) * 4;
            uint32_t sVh = sbase + (VTHI_OFF + half * 2176) * 4;
            uint32_t sVl = sbase + (VTLO_OFF + half * 2176) * 4;
            uint32_t aAddr = sP + (uint32_t)((wg * 16 + a7) * 272 + ahi16);
            uint32_t bAddrH = sVh + (uint32_t)(b7 * 272 + bhi16);
            uint32_t bAddrL = sVl + (uint32_t)(b7 * 272 + bhi16);

            float acc[4][4];
            #pragma unroll
            for (int nt = 0; nt < 4; nt++)
                #pragma unroll
                for (int t = 0; t < 4; t++) acc[nt][t] = 0.0f;

            #pragma unroll
            for (int ks = 0; ks < 8; ks++) {
                uint32_t a[4], ah[4], al[4];
                ldsm4(a[0], a[1], a[2], a[3], aAddr + ks * 32);
                #pragma unroll
                for (int t = 0; t < 4; t++) split_tf32(a[t], ah[t], al[t]);
                uint32_t bh[2][4], bl[2][4];
                #pragma unroll
                for (int p = 0; p < 2; p++) {
                    ldsm4(bh[p][0], bh[p][1], bh[p][2], bh[p][3],
                          bAddrH + (uint32_t)(p * 16 * 272) + ks * 32);
                    ldsm4(bl[p][0], bl[p][1], bl[p][2], bl[p][3],
                          bAddrL + (uint32_t)(p * 16 * 272) + ks * 32);
                }
                #pragma unroll
                for (int nt = 0; nt < 4; nt++) {
                    int p = nt >> 1, i0 = (nt & 1) * 2;
                    mma_tf32(acc[nt][0], acc[nt][1], acc[nt][2], acc[nt][3],
                             ah[0], ah[1], ah[2], ah[3], bh[p][i0], bh[p][i0 + 1]);
                    mma_tf32(acc[nt][0], acc[nt][1], acc[nt][2], acc[nt][3],
                             ah[0], ah[1], ah[2], ah[3], bl[p][i0], bl[p][i0 + 1]);
                    mma_tf32(acc[nt][0], acc[nt][1], acc[nt][2], acc[nt][3],
                             al[0], al[1], al[2], al[3], bh[p][i0], bh[p][i0 + 1]);
                }
            }

            int row = wg * 16 + er;
            float* og0 = g_xm + (size_t)(t0 + row) * 256 + head * 32;
            float* og1 = g_xm + (size_t)(t0 + row + 8) * 256 + head * 32;
            #pragma unroll
            for (int nt = 0; nt < 4; nt++) {
                int col = nt * 8 + ec;
                *(float2*)&og0[col] = make_float2(acc[nt][0], acc[nt][1]);
                *(float2*)&og1[col] = make_float2(acc[nt][2], acc[nt][3]);
            }
        }
    }
}

// ---------------- launch ----------------
extern "C" void kernel_launch(void* const* d_in, const int* in_sizes, int n_in,
                              void* d_out, int out_size)
{
    const float* x      = (const float*)d_in[0];
    const float* amask  = (const float*)d_in[1];
    const float* efeat  = (const float*)d_in[2];
    const float* qkv_w  = (const float*)d_in[3];
    const float* qkv_b  = (const float*)d_in[4];
    const float* proj_w = (const float*)d_in[5];
    const float* proj_b = (const float*)d_in[6];
    const float* eg_w1  = (const float*)d_in[7];
    const float* eg_b1  = (const float*)d_in[8];
    const float* eg_w2  = (const float*)d_in[9];
    const float* eg_b2  = (const float*)d_in[10];
    float* out = (float*)d_out;

    void* p_qkv = nullptr;
    void* p_xm  = nullptr;
    cudaGetSymbolAddress(&p_qkv, g_qkv);
    cudaGetSymbolAddress(&p_xm, g_xm);

    cudaFuncSetAttribute(attn_mma,
                         cudaFuncAttributeMaxDynamicSharedMemorySize, ATTN_SMEM);
    cudaFuncSetAttribute(gemm_tf32,
                         cudaFuncAttributeMaxDynamicSharedMemorySize, GEMM_SMEM);

    // 1) QKV projection (tf32 mma.sync, pre-converted staging)
    gemm_tf32<<<dim3(768 / 128, NTOK / 128), 256, GEMM_SMEM>>>(
        x, qkv_w, qkv_b, (float*)p_qkv, 768);

    // 2) edge gate ([blk][h][q][k] layout)
    gate_kernel<<<NBLK, 256>>>(amask, efeat, eg_w1, eg_b1, eg_w2, eg_b2);

    // 3) block attention (3xTF32, pre-split K/V)
    attn_mma<<<NBLK, 256, ATTN_SMEM>>>(amask, efeat);

    // 4) output projection
    gemm_tf32<<<dim3(CC / 128, NTOK / 128), 256, GEMM_SMEM>>>(
        (const float*)p_xm, proj_w, proj_b, out, CC);
}

// round 7
// speedup vs baseline: 2.3932x; 1.0403x over previous
#include <cuda_runtime.h>
#include <cuda_fp16.h>
#include <math.h>
#include <cstdint>

// Problem constants
#define BB    4
#define NTOK  32768          // B*N
#define CC    256
#define HH    8
#define HD    32
#define LL    64
#define NBLK  512            // B * NB
#define EGH   16

// ---------------- scratch (device globals; no allocs allowed) ----------------
__device__ float  g_qkv[(size_t)NTOK * 768];           // QKV gemm output (fp32)
__device__ float  g_xc[(size_t)NTOK * CC];             // x pre-rounded to tf32
__device__ float  g_wc[(size_t)(768 + 256) * CC];      // qkv_w | proj_w, tf32-rounded
__device__ __half g_gateh[(size_t)NBLK * 8 * 64 * 64]; // [blk][h][q][k] fp16
__device__ float  g_xm[(size_t)NTOK * CC];             // attn out (tf32-rounded)

// ======================= PTX helpers =======================
__device__ __forceinline__ uint32_t smem_to_u32(const void* p) {
    uint32_t a;
    asm("{ .reg .u64 t; cvta.to.shared.u64 t, %1; cvt.u32.u64 %0, t; }"
        : "=r"(a) : "l"(p));
    return a;
}

__device__ __forceinline__ void cp_async16(uint32_t smem_addr, const void* gptr) {
    asm volatile("cp.async.cg.shared.global [%0], [%1], 16;"
                 :: "r"(smem_addr), "l"(gptr));
}
#define CP_COMMIT() asm volatile("cp.async.commit_group;" ::: "memory")
#define CP_WAIT(n)  asm volatile("cp.async.wait_group %0;" :: "n"(n) : "memory")

__device__ __forceinline__ void ldsm4(uint32_t& r0, uint32_t& r1, uint32_t& r2,
                                      uint32_t& r3, uint32_t addr) {
    asm volatile("ldmatrix.sync.aligned.m8n8.x4.shared.b16 {%0,%1,%2,%3}, [%4];"
                 : "=r"(r0), "=r"(r1), "=r"(r2), "=r"(r3) : "r"(addr));
}

__device__ __forceinline__ uint32_t to_tf32(uint32_t x) {
    uint32_t y;
    asm("cvt.rna.tf32.f32 %0, %1;" : "=r"(y) : "r"(x));
    return y;
}

__device__ __forceinline__ float to_tf32f(float x) {
    return __uint_as_float(to_tf32(__float_as_uint(x)));
}

__device__ __forceinline__ void split_tf32(uint32_t x, uint32_t& hi, uint32_t& lo) {
    hi = to_tf32(x);
    float r = __uint_as_float(x) - __uint_as_float(hi);
    lo = to_tf32(__float_as_uint(r));
}

__device__ __forceinline__ void split4(float4 v, float4& hi, float4& lo) {
    hi.x = to_tf32f(v.x); lo.x = to_tf32f(v.x - hi.x);
    hi.y = to_tf32f(v.y); lo.y = to_tf32f(v.y - hi.y);
    hi.z = to_tf32f(v.z); lo.z = to_tf32f(v.z - hi.z);
    hi.w = to_tf32f(v.w); lo.w = to_tf32f(v.w - hi.w);
}

__device__ __forceinline__ void mma_tf32(float& c0, float& c1, float& c2, float& c3,
                                         uint32_t a0, uint32_t a1, uint32_t a2, uint32_t a3,
                                         uint32_t b0, uint32_t b1) {
    asm volatile(
        "mma.sync.aligned.m16n8k8.row.col.f32.tf32.tf32.f32 "
        "{%0,%1,%2,%3}, {%4,%5,%6,%7}, {%8,%9}, {%0,%1,%2,%3};"
        : "+f"(c0), "+f"(c1), "+f"(c2), "+f"(c3)
        : "r"(a0), "r"(a1), "r"(a2), "r"(a3), "r"(b0), "r"(b1));
}

// ---------------- tf32 pre-round pass ----------------
__global__ __launch_bounds__(256) void cvt_tf32_k(
    const float4* __restrict__ src, float4* __restrict__ dst, int n4)
{
    int i = blockIdx.x * blockDim.x + threadIdx.x;
    if (i < n4) {
        float4 v = src[i];
        v.x = to_tf32f(v.x); v.y = to_tf32f(v.y);
        v.z = to_tf32f(v.z); v.w = to_tf32f(v.w);
        dst[i] = v;
    }
}

// ============ tf32 GEMM on pre-rounded inputs: Y = X @ W^T + bias ============
// 128x128 tile / CTA, 256 thr (8 warps 2Mx4N), BK=32, 3-stage cp.async pipeline.
#define GEMM_TILE_B 16384                       // 128 rows * 128 bytes
#define GEMM_SMEM  (6 * GEMM_TILE_B)            // 3 stages x (A,B)

__device__ __forceinline__ void load_tile(const float* __restrict__ G, int row0,
                                          int k0, uint32_t s_tile, int tid) {
    #pragma unroll
    for (int i = 0; i < 4; i++) {
        int v = tid + i * 256;                   // 0..1023 float4 slots
        int r = v >> 3, c4 = v & 7;
        uint32_t dst = s_tile + (uint32_t)(r * 128 + ((c4 ^ (r & 7)) << 4));
        cp_async16(dst, G + (size_t)(row0 + r) * 256 + k0 + c4 * 4);
    }
}

__global__ __launch_bounds__(256) void gemm_cp(
    const float* __restrict__ X, const float* __restrict__ W,
    const float* __restrict__ bias, float* __restrict__ Y, int Nn)
{
    extern __shared__ char dsm[];
    uint32_t sbase = smem_to_u32(dsm);

    int tid = threadIdx.x;
    int wid = tid >> 5, lane = tid & 31;
    int warp_m = wid & 1;
    int warp_n = wid >> 1;
    int m0 = blockIdx.y * 128;
    int n0 = blockIdx.x * 128;

    int a_row = warp_m * 64 + (lane & 7) + ((lane >> 3) & 1) * 8;
    int a_hi = lane >> 4;
    int b_row = warp_n * 32 + ((lane >> 4) & 1) * 8 + (lane & 7);
    int b_hi = (lane >> 3) & 1;

    float acc[4][4][4];
    #pragma unroll
    for (int i = 0; i < 4; i++)
        #pragma unroll
        for (int j = 0; j < 4; j++)
            #pragma unroll
            for (int t = 0; t < 4; t++) acc[i][j][t] = 0.0f;

    // prologue: stages 0,1
    load_tile(X, m0, 0, sbase, tid);
    load_tile(W, n0, 0, sbase + GEMM_TILE_B, tid);
    CP_COMMIT();
    load_tile(X, m0, 32, sbase + 2 * GEMM_TILE_B, tid);
    load_tile(W, n0, 32, sbase + 3 * GEMM_TILE_B, tid);
    CP_COMMIT();

    #pragma unroll 1
    for (int c = 0; c < 8; c++) {
        if (c < 7) { CP_WAIT(1); } else { CP_WAIT(0); }
        __syncthreads();
        if (c + 2 < 8) {
            uint32_t st = sbase + (uint32_t)(((c + 2) % 3) * 2 * GEMM_TILE_B);
            load_tile(X, m0, (c + 2) * 32, st, tid);
            load_tile(W, n0, (c + 2) * 32, st + GEMM_TILE_B, tid);
            CP_COMMIT();
        }

        uint32_t sA = sbase + (uint32_t)((c % 3) * 2 * GEMM_TILE_B);
        uint32_t sB = sA + GEMM_TILE_B;

        #pragma unroll
        for (int ks = 0; ks < 4; ks++) {
            uint32_t a[4][4], b[2][4];
            #pragma unroll
            for (int mf = 0; mf < 4; mf++) {
                int m = a_row + mf * 16;
                uint32_t addr = sA + (uint32_t)(m * 128
                              + (((2 * ks + a_hi) ^ (m & 7)) << 4));
                ldsm4(a[mf][0], a[mf][1], a[mf][2], a[mf][3], addr);
            }
            #pragma unroll
            for (int p = 0; p < 2; p++) {
                int n = b_row + p * 16;
                uint32_t addr = sB + (uint32_t)(n * 128
                              + (((2 * ks + b_hi) ^ (n & 7)) << 4));
                ldsm4(b[p][0], b[p][1], b[p][2], b[p][3], addr);
            }
            #pragma unroll
            for (int mf = 0; mf < 4; mf++)
                #pragma unroll
                for (int nf = 0; nf < 4; nf++)
                    mma_tf32(acc[mf][nf][0], acc[mf][nf][1],
                             acc[mf][nf][2], acc[mf][nf][3],
                             a[mf][0], a[mf][1], a[mf][2], a[mf][3],
                             b[nf >> 1][(nf & 1) * 2], b[nf >> 1][(nf & 1) * 2 + 1]);
        }
    }

    int er = lane >> 2, ec = (lane & 3) * 2;
    #pragma unroll
    for (int mf = 0; mf < 4; mf++) {
        int row = m0 + warp_m * 64 + mf * 16 + er;
        #pragma unroll
        for (int nf = 0; nf < 4; nf++) {
            int col = n0 + warp_n * 32 + nf * 8 + ec;
            float2 bv = *(const float2*)&bias[col];
            float2 o0, o1;
            o0.x = acc[mf][nf][0] + bv.x;
            o0.y = acc[mf][nf][1] + bv.y;
            o1.x = acc[mf][nf][2] + bv.x;
            o1.y = acc[mf][nf][3] + bv.y;
            *(float2*)&Y[(size_t)row * Nn + col] = o0;
            *(float2*)&Y[(size_t)(row + 8) * Nn + col] = o1;
        }
    }
}

// ---------------- gate kernel: fp16 g[blk][h][q][k], masked --------------------
__global__ __launch_bounds__(256) void gate_kernel(
    const float* __restrict__ mask_g, const float* __restrict__ ef,
    const float* __restrict__ w1, const float* __restrict__ b1,
    const float* __restrict__ w2, const float* __restrict__ b2)
{
    __shared__ float sm[64 * 64];
    __shared__ float sw1[64], sb1[16], sw2[128], sb2[8];
    int blk = blockIdx.x;
    int tid = threadIdx.x;

    const float* mbase = mask_g + (size_t)blk * 4096;
    #pragma unroll
    for (int i = 0; i < 16; i++) sm[tid + i * 256] = mbase[tid + i * 256];
    if (tid < 64)  sw1[tid] = w1[tid];
    if (tid < 16)  sb1[tid] = b1[tid];
    if (tid < 128) sw2[tid] = w2[tid];
    if (tid < 8)   sb2[tid] = b2[tid];
    __syncthreads();

    if (tid < 64) {
        float s = 0.0f;
        for (int k = 0; k < 64; k++) s += sm[tid * 64 + k];
        if (s < 1.0f) sm[tid * 64 + tid] = 1.0f;
    }
    __syncthreads();

    for (int it = 0; it < 16; it++) {
        int idx = tid + it * 256;
        int q = idx >> 6, k = idx & 63;
        float m = sm[idx];
        float out[8];
        if (m == 0.0f) {
            #pragma unroll
            for (int h = 0; h < 8; h++) out[h] = 0.0f;
        } else {
            float e0, e1, e2, e3;
            if (q == k) { e0 = e1 = e2 = 0.0f; e3 = 1.0f; }
            else {
                float4 ev = *(const float4*)(ef + ((size_t)blk * 4096 + idx) * 4);
                e0 = ev.x; e1 = ev.y; e2 = ev.z; e3 = ev.w;
            }
            float hh[16];
            #pragma unroll
            for (int j = 0; j < 16; j++) {
                float t = sb1[j] + sw1[j * 4] * e0 + sw1[j * 4 + 1] * e1
                        + sw1[j * 4 + 2] * e2 + sw1[j * 4 + 3] * e3;
                hh[j] = 0.5f * t * (1.0f + erff(t * 0.70710678118654752f));
            }
            #pragma unroll
            for (int h = 0; h < 8; h++) {
                float s = sb2[h];
                #pragma unroll
                for (int j = 0; j < 16; j++) s += sw2[h * 16 + j] * hh[j];
                out[h] = s;
            }
        }
        __half* gp = g_gateh + (size_t)blk * 32768 + idx;
        #pragma unroll
        for (int h = 0; h < 8; h++) gp[h * 4096] = __float2half_rn(out[h]);
    }
}

// ---------------- attention kernel (tensor-core 3xTF32) --------------------
#define SB_OFF    0                 // [64][66]
#define SC_OFF    4224              // [2][64][68]
#define QH_OFF    12928             // [2][64][36]
#define KHI_OFF   17536             // [2][64][36]
#define KLO_OFF   22144             // [2][64][36]
#define VTHI_OFF  26752             // [2][32][68]
#define VTLO_OFF  31104             // [2][32][68]
#define ATTN_FLOATS 35456
#define ATTN_SMEM (ATTN_FLOATS * 4)

__global__ __launch_bounds__(256) void attn_mma(
    const float* __restrict__ mask_g, const float* __restrict__ ef)
{
    extern __shared__ float smf[];
    uint32_t sbase = smem_to_u32(smf);

    int blk = blockIdx.x;
    int tid = threadIdx.x;
    int wid = tid >> 5, lane = tid & 31;
    int half = wid >> 2;
    int wg = wid & 3;
    int t0 = blk * 64;

    #pragma unroll
    for (int i = 0; i < 16; i++) {
        int idx = tid + i * 256;
        smf[SB_OFF + (idx >> 6) * 66 + (idx & 63)] = mask_g[(size_t)blk * 4096 + idx];
    }
    __syncthreads();
    if (tid < 64) {
        float s = 0.0f;
        for (int k = 0; k < 64; k++) s += smf[SB_OFF + tid * 66 + k];
        if (s < 1.0f) smf[SB_OFF + tid * 66 + tid] = 1.0f;
    }
    __syncthreads();
    #pragma unroll
    for (int i = 0; i < 16; i++) {
        int idx = tid + i * 256;
        int q = idx >> 6, k = idx & 63;
        float m = smf[SB_OFF + q * 66 + k];
        float bias = (q == k) ? 1.0f : ef[((size_t)blk * 4096 + idx) * 4 + 3];
        smf[SB_OFF + q * 66 + k] = (m == 0.0f) ? -1e30f : bias;
    }

    const float scale = 0.17677669529663687f;

    int a7 = (lane & 7) + ((lane >> 3) & 1) * 8;
    int ahi16 = (lane >> 4) * 16;
    int b7 = (lane & 7) + ((lane >> 4) & 1) * 8;
    int bhi16 = ((lane >> 3) & 1) * 16;
    int er = lane >> 2, ec = (lane & 3) * 2;

    #pragma unroll 1
    for (int it = 0; it < 4; it++) {
        __syncthreads();

        // ---- stage Q (fp32) and pre-split K, V^T for heads 2it, 2it+1 ----
        #pragma unroll
        for (int j = 0; j < 4; j++) {
            int idx = tid + j * 256;
            int sh = idx >> 9;
            int rem = idx & 511;
            int t = rem >> 3, c4 = rem & 7;
            int head = it * 2 + sh;
            const float* src = g_qkv + (size_t)(t0 + t) * 768 + head * 32 + c4 * 4;
            float4 qv = *(const float4*)(src);
            float4 kv = *(const float4*)(src + 256);
            float4 vv = *(const float4*)(src + 512);
            *(float4*)&smf[QH_OFF + sh * 2304 + t * 36 + c4 * 4] = qv;
            float4 khi, klo; split4(kv, khi, klo);
            *(float4*)&smf[KHI_OFF + sh * 2304 + t * 36 + c4 * 4] = khi;
            *(float4*)&smf[KLO_OFF + sh * 2304 + t * 36 + c4 * 4] = klo;
            float4 vhi, vlo; split4(vv, vhi, vlo);
            float* vh = &smf[VTHI_OFF + sh * 2176 + (c4 * 4) * 68 + t];
            vh[0] = vhi.x; vh[68] = vhi.y; vh[136] = vhi.z; vh[204] = vhi.w;
            float* vl = &smf[VTLO_OFF + sh * 2176 + (c4 * 4) * 68 + t];
            vl[0] = vlo.x; vl[68] = vlo.y; vl[136] = vlo.z; vl[204] = vlo.w;
        }
        __syncthreads();

        int head = it * 2 + half;

        // ---- QK^T (3xTF32) ----
        {
            uint32_t sQ = sbase + (QH_OFF + half * 2304) * 4;
            uint32_t sKh = sbase + (KHI_OFF + half * 2304) * 4;
            uint32_t sKl = sbase + (KLO_OFF + half * 2304) * 4;
            uint32_t aAddr = sQ + (uint32_t)((wg * 16 + a7) * 144 + ahi16);
            uint32_t bAddrH = sKh + (uint32_t)(b7 * 144 + bhi16);
            uint32_t bAddrL = sKl + (uint32_t)(b7 * 144 + bhi16);

            float acc[8][4];
            #pragma unroll
            for (int nt = 0; nt < 8; nt++)
                #pragma unroll
                for (int t = 0; t < 4; t++) acc[nt][t] = 0.0f;

            #pragma unroll
            for (int ks = 0; ks < 4; ks++) {
                uint32_t a[4], ah[4], al[4];
                ldsm4(a[0], a[1], a[2], a[3], aAddr + ks * 32);
                #pragma unroll
                for (int t = 0; t < 4; t++) split_tf32(a[t], ah[t], al[t]);
                uint32_t bh[4][4], bl[4][4];
                #pragma unroll
                for (int p = 0; p < 4; p++) {
                    ldsm4(bh[p][0], bh[p][1], bh[p][2], bh[p][3],
                          bAddrH + (uint32_t)(p * 16 * 144) + ks * 32);
                    ldsm4(bl[p][0], bl[p][1], bl[p][2], bl[p][3],
                          bAddrL + (uint32_t)(p * 16 * 144) + ks * 32);
                }
                #pragma unroll
                for (int nt = 0; nt < 8; nt++) {
                    int p = nt >> 1, i0 = (nt & 1) * 2;
                    mma_tf32(acc[nt][0], acc[nt][1], acc[nt][2], acc[nt][3],
                             ah[0], ah[1], ah[2], ah[3], bh[p][i0], bh[p][i0 + 1]);
                    mma_tf32(acc[nt][0], acc[nt][1], acc[nt][2], acc[nt][3],
                             ah[0], ah[1], ah[2], ah[3], bl[p][i0], bl[p][i0 + 1]);
                    mma_tf32(acc[nt][0], acc[nt][1], acc[nt][2], acc[nt][3],
                             al[0], al[1], al[2], al[3], bh[p][i0], bh[p][i0 + 1]);
                }
            }

            float* Scm = &smf[SC_OFF + half * 4352];
            int row = wg * 16 + er;
            #pragma unroll
            for (int nt = 0; nt < 8; nt++) {
                int col = nt * 8 + ec;
                float2 s0 = *(float2*)&smf[SB_OFF + row * 66 + col];
                float2 s1 = *(float2*)&smf[SB_OFF + (row + 8) * 66 + col];
                float2 o0, o1;
                o0.x = acc[nt][0] * scale + s0.x;
                o0.y = acc[nt][1] * scale + s0.y;
                o1.x = acc[nt][2] * scale + s1.x;
                o1.y = acc[nt][3] * scale + s1.y;
                *(float2*)&Scm[row * 68 + col] = o0;
                *(float2*)&Scm[(row + 8) * 68 + col] = o1;
            }
        }
        __syncthreads();

        // ---- softmax + gate add (vectorized; 32-byte gate read) ----
        #pragma unroll 1
        for (int sh = 0; sh < 2; sh++) {
            float* Scm = &smf[SC_OFF + sh * 4352];
            int hh2 = it * 2 + sh;
            int qq = tid >> 2, quad = tid & 3;
            float vals[16];
            #pragma unroll
            for (int i = 0; i < 4; i++)
                *(float4*)&vals[i * 4] = *(const float4*)&Scm[qq * 68 + quad * 16 + i * 4];
            float vmax = -3.0e38f;
            #pragma unroll
            for (int i = 0; i < 16; i++) vmax = fmaxf(vmax, vals[i]);
            vmax = fmaxf(vmax, __shfl_xor_sync(0xffffffffu, vmax, 1));
            vmax = fmaxf(vmax, __shfl_xor_sync(0xffffffffu, vmax, 2));
            float ssum = 0.0f;
            #pragma unroll
            for (int i = 0; i < 16; i++) {
                float e = __expf(vals[i] - vmax);
                vals[i] = e;
                ssum += e;
            }
            ssum += __shfl_xor_sync(0xffffffffu, ssum, 1);
            ssum += __shfl_xor_sync(0xffffffffu, ssum, 2);
            float inv = 1.0f / ssum;

            // 16 halves = 32 bytes -> two uint4 loads
            const __half* gb = g_gateh + (size_t)blk * 32768 + (size_t)hh2 * 4096
                             + qq * 64 + quad * 16;
            uint4 gw0 = *(const uint4*)gb;
            uint4 gw1 = *(const uint4*)(gb + 8);
            float gv[16];
            {
                const __half2* hp0 = (const __half2*)&gw0;
                const __half2* hp1 = (const __half2*)&gw1;
                #pragma unroll
                for (int j = 0; j < 4; j++) {
                    float2 f0 = __half22float2(hp0[j]);
                    gv[2 * j] = f0.x; gv[2 * j + 1] = f0.y;
                    float2 f1 = __half22float2(hp1[j]);
                    gv[8 + 2 * j] = f1.x; gv[8 + 2 * j + 1] = f1.y;
                }
            }
            #pragma unroll
            for (int i = 0; i < 4; i++) {
                float4 o;
                o.x = vals[i * 4 + 0] * inv + gv[i * 4 + 0];
                o.y = vals[i * 4 + 1] * inv + gv[i * 4 + 1];
                o.z = vals[i * 4 + 2] * inv + gv[i * 4 + 2];
                o.w = vals[i * 4 + 3] * inv + gv[i * 4 + 3];
                *(float4*)&Scm[qq * 68 + quad * 16 + i * 4] = o;
            }
        }
        __syncthreads();

        // ---- PV (3xTF32) ----
        {
            uint32_t sP = sbase + (SC_OFF + half * 4352) * 4;
            uint32_t sVh = sbase + (VTHI_OFF + half * 2176) * 4;
            uint32_t sVl = sbase + (VTLO_OFF + half * 2176) * 4;
            uint32_t aAddr = sP + (uint32_t)((wg * 16 + a7) * 272 + ahi16);
            uint32_t bAddrH = sVh + (uint32_t)(b7 * 272 + bhi16);
            uint32_t bAddrL = sVl + (uint32_t)(b7 * 272 + bhi16);

            float acc[4][4];
            #pragma unroll
            for (int nt = 0; nt < 4; nt++)
                #pragma unroll
                for (int t = 0; t < 4; t++) acc[nt][t] = 0.0f;

            #pragma unroll
            for (int ks = 0; ks < 8; ks++) {
                uint32_t a[4], ah[4], al[4];
                ldsm4(a[0], a[1], a[2], a[3], aAddr + ks * 32);
                #pragma unroll
                for (int t = 0; t < 4; t++) split_tf32(a[t], ah[t], al[t]);
                uint32_t bh[2][4], bl[2][4];
                #pragma unroll
                for (int p = 0; p < 2; p++) {
                    ldsm4(bh[p][0], bh[p][1], bh[p][2], bh[p][3],
                          bAddrH + (uint32_t)(p * 16 * 272) + ks * 32);
                    ldsm4(bl[p][0], bl[p][1], bl[p][2], bl[p][3],
                          bAddrL + (uint32_t)(p * 16 * 272) + ks * 32);
                }
                #pragma unroll
                for (int nt = 0; nt < 4; nt++) {
                    int p = nt >> 1, i0 = (nt & 1) * 2;
                    mma_tf32(acc[nt][0], acc[nt][1], acc[nt][2], acc[nt][3],
                             ah[0], ah[1], ah[2], ah[3], bh[p][i0], bh[p][i0 + 1]);
                    mma_tf32(acc[nt][0], acc[nt][1], acc[nt][2], acc[nt][3],
                             ah[0], ah[1], ah[2], ah[3], bl[p][i0], bl[p][i0 + 1]);
                    mma_tf32(acc[nt][0], acc[nt][1], acc[nt][2], acc[nt][3],
                             al[0], al[1], al[2], al[3], bh[p][i0], bh[p][i0 + 1]);
                }
            }

            // write g_xm pre-rounded to tf32 (proj GEMM consumes without cvt)
            int row = wg * 16 + er;
            float* og0 = g_xm + (size_t)(t0 + row) * 256 + head * 32;
            float* og1 = g_xm + (size_t)(t0 + row + 8) * 256 + head * 32;
            #pragma unroll
            for (int nt = 0; nt < 4; nt++) {
                int col = nt * 8 + ec;
                *(float2*)&og0[col] = make_float2(to_tf32f(acc[nt][0]),
                                                  to_tf32f(acc[nt][1]));
                *(float2*)&og1[col] = make_float2(to_tf32f(acc[nt][2]),
                                                  to_tf32f(acc[nt][3]));
            }
        }
    }
}

// ---------------- launch ----------------
extern "C" void kernel_launch(void* const* d_in, const int* in_sizes, int n_in,
                              void* d_out, int out_size)
{
    const float* x      = (const float*)d_in[0];
    const float* amask  = (const float*)d_in[1];
    const float* efeat  = (const float*)d_in[2];
    const float* qkv_w  = (const float*)d_in[3];
    const float* qkv_b  = (const float*)d_in[4];
    const float* proj_w = (const float*)d_in[5];
    const float* proj_b = (const float*)d_in[6];
    const float* eg_w1  = (const float*)d_in[7];
    const float* eg_b1  = (const float*)d_in[8];
    const float* eg_w2  = (const float*)d_in[9];
    const float* eg_b2  = (const float*)d_in[10];
    float* out = (float*)d_out;

    void* p_qkv = nullptr; void* p_xc = nullptr; void* p_wc = nullptr;
    void* p_xm  = nullptr;
    cudaGetSymbolAddress(&p_qkv, g_qkv);
    cudaGetSymbolAddress(&p_xc, g_xc);
    cudaGetSymbolAddress(&p_wc, g_wc);
    cudaGetSymbolAddress(&p_xm, g_xm);
    float* xc = (float*)p_xc;
    float* wc = (float*)p_wc;

    cudaFuncSetAttribute(attn_mma,
                         cudaFuncAttributeMaxDynamicSharedMemorySize, ATTN_SMEM);
    cudaFuncSetAttribute(gemm_cp,
                         cudaFuncAttributeMaxDynamicSharedMemorySize, GEMM_SMEM);

    // 0) pre-round x and weights to tf32
    cvt_tf32_k<<<(NTOK * CC / 4 + 255) / 256, 256>>>(
        (const float4*)x, (float4*)xc, NTOK * CC / 4);
    cvt_tf32_k<<<(768 * CC / 4 + 255) / 256, 256>>>(
        (const float4*)qkv_w, (float4*)wc, 768 * CC / 4);
    cvt_tf32_k<<<(CC * CC / 4 + 255) / 256, 256>>>(
        (const float4*)proj_w, (float4*)(wc + 768 * CC), CC * CC / 4);

    // 1) QKV projection (pure cp.async tf32 GEMM)
    gemm_cp<<<dim3(768 / 128, NTOK / 128), 256, GEMM_SMEM>>>(
        xc, wc, qkv_b, (float*)p_qkv, 768);

    // 2) edge gate (fp16 out, [blk][h][q][k])
    gate_kernel<<<NBLK, 256>>>(amask, efeat, eg_w1, eg_b1, eg_w2, eg_b2);

    // 3) block attention (3xTF32, writes tf32-rounded g_xm)
    attn_mma<<<NBLK, 256, ATTN_SMEM>>>(amask, efeat);

    // 4) output projection
    gemm_cp<<<dim3(CC / 128, NTOK / 128), 256, GEMM_SMEM>>>(
        (const float*)p_xm, wc + 768 * CC, proj_b, out, CC);
}

// round 8
// speedup vs baseline: 2.6591x; 1.1111x over previous
#include <cuda_runtime.h>
#include <cuda_fp16.h>
#include <math.h>
#include <cstdint>

// Problem constants
#define BB    4
#define NTOK  32768          // B*N
#define CC    256
#define HH    8
#define HD    32
#define LL    64
#define NBLK  512            // B * NB
#define EGH   16

// ---------------- scratch (device globals; no allocs allowed) ----------------
__device__ float  g_qkv[(size_t)NTOK * 768];           // QKV gemm output (fp32)
__device__ float  g_xc[(size_t)NTOK * CC];             // x pre-rounded to tf32
__device__ float  g_wc[(size_t)(768 + 256) * CC];      // qkv_w | proj_w, tf32-rounded
__device__ __half g_gateh[(size_t)NBLK * 8 * 64 * 64]; // [blk][h][q][k] fp16
__device__ float  g_bias[(size_t)NBLK * 64 * 64];      // [blk][q][k] bias or -1e30
__device__ float  g_xm[(size_t)NTOK * CC];             // attn out (tf32-rounded)

// ======================= PTX helpers =======================
__device__ __forceinline__ uint32_t smem_to_u32(const void* p) {
    uint32_t a;
    asm("{ .reg .u64 t; cvta.to.shared.u64 t, %1; cvt.u32.u64 %0, t; }"
        : "=r"(a) : "l"(p));
    return a;
}

__device__ __forceinline__ void cp_async16(uint32_t smem_addr, const void* gptr) {
    asm volatile("cp.async.cg.shared.global [%0], [%1], 16;"
                 :: "r"(smem_addr), "l"(gptr));
}
#define CP_COMMIT() asm volatile("cp.async.commit_group;" ::: "memory")
#define CP_WAIT(n)  asm volatile("cp.async.wait_group %0;" :: "n"(n) : "memory")

__device__ __forceinline__ void ldsm4(uint32_t& r0, uint32_t& r1, uint32_t& r2,
                                      uint32_t& r3, uint32_t addr) {
    asm volatile("ldmatrix.sync.aligned.m8n8.x4.shared.b16 {%0,%1,%2,%3}, [%4];"
                 : "=r"(r0), "=r"(r1), "=r"(r2), "=r"(r3) : "r"(addr));
}

__device__ __forceinline__ uint32_t to_tf32(uint32_t x) {
    uint32_t y;
    asm("cvt.rna.tf32.f32 %0, %1;" : "=r"(y) : "r"(x));
    return y;
}

__device__ __forceinline__ float to_tf32f(float x) {
    return __uint_as_float(to_tf32(__float_as_uint(x)));
}

__device__ __forceinline__ void split_tf32(uint32_t x, uint32_t& hi, uint32_t& lo) {
    hi = to_tf32(x);
    float r = __uint_as_float(x) - __uint_as_float(hi);
    lo = to_tf32(__float_as_uint(r));
}

__device__ __forceinline__ void split4(float4 v, float4& hi, float4& lo) {
    hi.x = to_tf32f(v.x); lo.x = to_tf32f(v.x - hi.x);
    hi.y = to_tf32f(v.y); lo.y = to_tf32f(v.y - hi.y);
    hi.z = to_tf32f(v.z); lo.z = to_tf32f(v.z - hi.z);
    hi.w = to_tf32f(v.w); lo.w = to_tf32f(v.w - hi.w);
}

__device__ __forceinline__ void mma_tf32(float& c0, float& c1, float& c2, float& c3,
                                         uint32_t a0, uint32_t a1, uint32_t a2, uint32_t a3,
                                         uint32_t b0, uint32_t b1) {
    asm volatile(
        "mma.sync.aligned.m16n8k8.row.col.f32.tf32.tf32.f32 "
        "{%0,%1,%2,%3}, {%4,%5,%6,%7}, {%8,%9}, {%0,%1,%2,%3};"
        : "+f"(c0), "+f"(c1), "+f"(c2), "+f"(c3)
        : "r"(a0), "r"(a1), "r"(a2), "r"(a3), "r"(b0), "r"(b1));
}

// ---------------- tf32 pre-round pass ----------------
__global__ __launch_bounds__(256) void cvt_tf32_k(
    const float4* __restrict__ src, float4* __restrict__ dst, int n4)
{
    int i = blockIdx.x * blockDim.x + threadIdx.x;
    if (i < n4) {
        float4 v = src[i];
        v.x = to_tf32f(v.x); v.y = to_tf32f(v.y);
        v.z = to_tf32f(v.z); v.w = to_tf32f(v.w);
        dst[i] = v;
    }
}

// ============ tf32 GEMM on pre-rounded inputs: Y = X @ W^T + bias ============
#define GEMM_TILE_B 16384                       // 128 rows * 128 bytes
#define GEMM_SMEM  (6 * GEMM_TILE_B)            // 3 stages x (A,B)

__device__ __forceinline__ void load_tile(const float* __restrict__ G, int row0,
                                          int k0, uint32_t s_tile, int tid) {
    #pragma unroll
    for (int i = 0; i < 4; i++) {
        int v = tid + i * 256;                   // 0..1023 float4 slots
        int r = v >> 3, c4 = v & 7;
        uint32_t dst = s_tile + (uint32_t)(r * 128 + ((c4 ^ (r & 7)) << 4));
        cp_async16(dst, G + (size_t)(row0 + r) * 256 + k0 + c4 * 4);
    }
}

__global__ __launch_bounds__(256) void gemm_cp(
    const float* __restrict__ X, const float* __restrict__ W,
    const float* __restrict__ bias, float* __restrict__ Y, int Nn)
{
    extern __shared__ char dsm[];
    uint32_t sbase = smem_to_u32(dsm);

    int tid = threadIdx.x;
    int wid = tid >> 5, lane = tid & 31;
    int warp_m = wid & 1;
    int warp_n = wid >> 1;
    int m0 = blockIdx.y * 128;
    int n0 = blockIdx.x * 128;

    int a_row = warp_m * 64 + (lane & 7) + ((lane >> 3) & 1) * 8;
    int a_hi = lane >> 4;
    int b_row = warp_n * 32 + ((lane >> 4) & 1) * 8 + (lane & 7);
    int b_hi = (lane >> 3) & 1;

    float acc[4][4][4];
    #pragma unroll
    for (int i = 0; i < 4; i++)
        #pragma unroll
        for (int j = 0; j < 4; j++)
            #pragma unroll
            for (int t = 0; t < 4; t++) acc[i][j][t] = 0.0f;

    load_tile(X, m0, 0, sbase, tid);
    load_tile(W, n0, 0, sbase + GEMM_TILE_B, tid);
    CP_COMMIT();
    load_tile(X, m0, 32, sbase + 2 * GEMM_TILE_B, tid);
    load_tile(W, n0, 32, sbase + 3 * GEMM_TILE_B, tid);
    CP_COMMIT();

    #pragma unroll 1
    for (int c = 0; c < 8; c++) {
        if (c < 7) { CP_WAIT(1); } else { CP_WAIT(0); }
        __syncthreads();
        if (c + 2 < 8) {
            uint32_t st = sbase + (uint32_t)(((c + 2) % 3) * 2 * GEMM_TILE_B);
            load_tile(X, m0, (c + 2) * 32, st, tid);
            load_tile(W, n0, (c + 2) * 32, st + GEMM_TILE_B, tid);
            CP_COMMIT();
        }

        uint32_t sA = sbase + (uint32_t)((c % 3) * 2 * GEMM_TILE_B);
        uint32_t sB = sA + GEMM_TILE_B;

        #pragma unroll
        for (int ks = 0; ks < 4; ks++) {
            uint32_t a[4][4], b[2][4];
            #pragma unroll
            for (int mf = 0; mf < 4; mf++) {
                int m = a_row + mf * 16;
                uint32_t addr = sA + (uint32_t)(m * 128
                              + (((2 * ks + a_hi) ^ (m & 7)) << 4));
                ldsm4(a[mf][0], a[mf][1], a[mf][2], a[mf][3], addr);
            }
            #pragma unroll
            for (int p = 0; p < 2; p++) {
                int n = b_row + p * 16;
                uint32_t addr = sB + (uint32_t)(n * 128
                              + (((2 * ks + b_hi) ^ (n & 7)) << 4));
                ldsm4(b[p][0], b[p][1], b[p][2], b[p][3], addr);
            }
            #pragma unroll
            for (int mf = 0; mf < 4; mf++)
                #pragma unroll
                for (int nf = 0; nf < 4; nf++)
                    mma_tf32(acc[mf][nf][0], acc[mf][nf][1],
                             acc[mf][nf][2], acc[mf][nf][3],
                             a[mf][0], a[mf][1], a[mf][2], a[mf][3],
                             b[nf >> 1][(nf & 1) * 2], b[nf >> 1][(nf & 1) * 2 + 1]);
        }
    }

    int er = lane >> 2, ec = (lane & 3) * 2;
    #pragma unroll
    for (int mf = 0; mf < 4; mf++) {
        int row = m0 + warp_m * 64 + mf * 16 + er;
        #pragma unroll
        for (int nf = 0; nf < 4; nf++) {
            int col = n0 + warp_n * 32 + nf * 8 + ec;
            float2 bv = *(const float2*)&bias[col];
            float2 o0, o1;
            o0.x = acc[mf][nf][0] + bv.x;
            o0.y = acc[mf][nf][1] + bv.y;
            o1.x = acc[mf][nf][2] + bv.x;
            o1.y = acc[mf][nf][3] + bv.y;
            *(float2*)&Y[(size_t)row * Nn + col] = o0;
            *(float2*)&Y[(size_t)(row + 8) * Nn + col] = o1;
        }
    }
}

// ------- gate kernel: fp16 g[blk][h][q][k] + fp32 bias[blk][q][k] -------
__global__ __launch_bounds__(256) void gate_kernel(
    const float* __restrict__ mask_g, const float* __restrict__ ef,
    const float* __restrict__ w1, const float* __restrict__ b1,
    const float* __restrict__ w2, const float* __restrict__ b2)
{
    __shared__ float sm[64 * 64];
    __shared__ float sw1[64], sb1[16], sw2[128], sb2[8];
    int blk = blockIdx.x;
    int tid = threadIdx.x;

    const float* mbase = mask_g + (size_t)blk * 4096;
    #pragma unroll
    for (int i = 0; i < 16; i++) sm[tid + i * 256] = mbase[tid + i * 256];
    if (tid < 64)  sw1[tid] = w1[tid];
    if (tid < 16)  sb1[tid] = b1[tid];
    if (tid < 128) sw2[tid] = w2[tid];
    if (tid < 8)   sb2[tid] = b2[tid];
    __syncthreads();

    if (tid < 64) {
        float s = 0.0f;
        for (int k = 0; k < 64; k++) s += sm[tid * 64 + k];
        if (s < 1.0f) sm[tid * 64 + tid] = 1.0f;
    }
    __syncthreads();

    for (int it = 0; it < 16; it++) {
        int idx = tid + it * 256;
        int q = idx >> 6, k = idx & 63;
        float m = sm[idx];
        float out[8];
        float bias;
        if (m == 0.0f) {
            bias = -1e30f;
            #pragma unroll
            for (int h = 0; h < 8; h++) out[h] = 0.0f;
        } else {
            float e0, e1, e2, e3;
            if (q == k) { e0 = e1 = e2 = 0.0f; e3 = 1.0f; }
            else {
                float4 ev = *(const float4*)(ef + ((size_t)blk * 4096 + idx) * 4);
                e0 = ev.x; e1 = ev.y; e2 = ev.z; e3 = ev.w;
            }
            bias = e3;
            float hh[16];
            #pragma unroll
            for (int j = 0; j < 16; j++) {
                float t = sb1[j] + sw1[j * 4] * e0 + sw1[j * 4 + 1] * e1
                        + sw1[j * 4 + 2] * e2 + sw1[j * 4 + 3] * e3;
                hh[j] = 0.5f * t * (1.0f + erff(t * 0.70710678118654752f));
            }
            #pragma unroll
            for (int h = 0; h < 8; h++) {
                float s = sb2[h];
                #pragma unroll
                for (int j = 0; j < 16; j++) s += sw2[h * 16 + j] * hh[j];
                out[h] = s;
            }
        }
        g_bias[(size_t)blk * 4096 + idx] = bias;
        __half* gp = g_gateh + (size_t)blk * 32768 + idx;
        #pragma unroll
        for (int h = 0; h < 8; h++) gp[h * 4096] = __float2half_rn(out[h]);
    }
}

// ---------------- attention kernel (register softmax, 2 CTAs/SM) ----------------
#define SC_OFF    0                 // [2][64][68]  P (probs+gate)
#define QH_OFF    8704              // [2][64][36]  Q raw fp32
#define KR_OFF    13312             // [2][64][36]  K raw fp32
#define VTHI_OFF  17920             // [2][32][68]  V^T tf32-hi
#define VTLO_OFF  22272             // [2][32][68]  V^T tf32-lo
#define ATTN_FLOATS 26624
#define ATTN_SMEM (ATTN_FLOATS * 4) // 104 KB -> 2 CTAs/SM

__global__ __launch_bounds__(256, 2) void attn_mma(
    const float* __restrict__ bias_g)
{
    extern __shared__ float smf[];
    uint32_t sbase = smem_to_u32(smf);

    int blk = blockIdx.x;
    int tid = threadIdx.x;
    int wid = tid >> 5, lane = tid & 31;
    int half = wid >> 2;
    int wg = wid & 3;
    int t0 = blk * 64;

    const float scale = 0.17677669529663687f;

    int a7 = (lane & 7) + ((lane >> 3) & 1) * 8;
    int ahi16 = (lane >> 4) * 16;
    int b7 = (lane & 7) + ((lane >> 4) & 1) * 8;
    int bhi16 = ((lane >> 3) & 1) * 16;
    int er = lane >> 2, ec = (lane & 3) * 2;

    #pragma unroll 1
    for (int it = 0; it < 4; it++) {
        if (it) __syncthreads();                 // prev iter done with tiles

        // ---- stage Q, K raw + pre-split V^T for heads 2it, 2it+1 ----
        #pragma unroll
        for (int j = 0; j < 4; j++) {
            int idx = tid + j * 256;
            int sh = idx >> 9;
            int rem = idx & 511;
            int t = rem >> 3, c4 = rem & 7;
            int head = it * 2 + sh;
            const float* src = g_qkv + (size_t)(t0 + t) * 768 + head * 32 + c4 * 4;
            float4 qv = *(const float4*)(src);
            float4 kv = *(const float4*)(src + 256);
            float4 vv = *(const float4*)(src + 512);
            *(float4*)&smf[QH_OFF + sh * 2304 + t * 36 + c4 * 4] = qv;
            *(float4*)&smf[KR_OFF + sh * 2304 + t * 36 + c4 * 4] = kv;
            float4 vhi, vlo; split4(vv, vhi, vlo);
            float* vh = &smf[VTHI_OFF + sh * 2176 + (c4 * 4) * 68 + t];
            vh[0] = vhi.x; vh[68] = vhi.y; vh[136] = vhi.z; vh[204] = vhi.w;
            float* vl = &smf[VTLO_OFF + sh * 2176 + (c4 * 4) * 68 + t];
            vl[0] = vlo.x; vl[68] = vlo.y; vl[136] = vlo.z; vl[204] = vlo.w;
        }
        __syncthreads();

        int head = it * 2 + half;

        // ---- QK^T (3xTF32), rows [wg*16,+16) x all 64 cols ----
        float acc[8][4];
        #pragma unroll
        for (int nt = 0; nt < 8; nt++)
            #pragma unroll
            for (int t = 0; t < 4; t++) acc[nt][t] = 0.0f;
        {
            uint32_t sQ = sbase + (QH_OFF + half * 2304) * 4;
            uint32_t sK = sbase + (KR_OFF + half * 2304) * 4;
            uint32_t aAddr = sQ + (uint32_t)((wg * 16 + a7) * 144 + ahi16);
            uint32_t bAddr = sK + (uint32_t)(b7 * 144 + bhi16);

            #pragma unroll
            for (int ks = 0; ks < 4; ks++) {
                uint32_t a[4], ah[4], al[4];
                ldsm4(a[0], a[1], a[2], a[3], aAddr + ks * 32);
                #pragma unroll
                for (int t = 0; t < 4; t++) split_tf32(a[t], ah[t], al[t]);
                uint32_t bh[4][4], bl[4][4];
                #pragma unroll
                for (int p = 0; p < 4; p++) {
                    uint32_t braw[4];
                    ldsm4(braw[0], braw[1], braw[2], braw[3],
                          bAddr + (uint32_t)(p * 16 * 144) + ks * 32);
                    #pragma unroll
                    for (int t = 0; t < 4; t++)
                        split_tf32(braw[t], bh[p][t], bl[p][t]);
                }
                #pragma unroll
                for (int nt = 0; nt < 8; nt++) {
                    int p = nt >> 1, i0 = (nt & 1) * 2;
                    mma_tf32(acc[nt][0], acc[nt][1], acc[nt][2], acc[nt][3],
                             ah[0], ah[1], ah[2], ah[3], bh[p][i0], bh[p][i0 + 1]);
                    mma_tf32(acc[nt][0], acc[nt][1], acc[nt][2], acc[nt][3],
                             ah[0], ah[1], ah[2], ah[3], bl[p][i0], bl[p][i0 + 1]);
                    mma_tf32(acc[nt][0], acc[nt][1], acc[nt][2], acc[nt][3],
                             al[0], al[1], al[2], al[3], bh[p][i0], bh[p][i0 + 1]);
                }
            }
        }

        // ---- bias + softmax + gate, entirely in registers ----
        int r0 = wg * 16 + er;
        {
            const float* bb = bias_g + (size_t)blk * 4096;
            float m0 = -3.0e38f, m1 = -3.0e38f;
            #pragma unroll
            for (int nt = 0; nt < 8; nt++) {
                int col = nt * 8 + ec;
                float2 b0 = *(const float2*)&bb[r0 * 64 + col];
                float2 b1 = *(const float2*)&bb[(r0 + 8) * 64 + col];
                acc[nt][0] = acc[nt][0] * scale + b0.x;
                acc[nt][1] = acc[nt][1] * scale + b0.y;
                acc[nt][2] = acc[nt][2] * scale + b1.x;
                acc[nt][3] = acc[nt][3] * scale + b1.y;
                m0 = fmaxf(m0, fmaxf(acc[nt][0], acc[nt][1]));
                m1 = fmaxf(m1, fmaxf(acc[nt][2], acc[nt][3]));
            }
            m0 = fmaxf(m0, __shfl_xor_sync(0xffffffffu, m0, 1));
            m0 = fmaxf(m0, __shfl_xor_sync(0xffffffffu, m0, 2));
            m1 = fmaxf(m1, __shfl_xor_sync(0xffffffffu, m1, 1));
            m1 = fmaxf(m1, __shfl_xor_sync(0xffffffffu, m1, 2));
            float s0 = 0.0f, s1 = 0.0f;
            #pragma unroll
            for (int nt = 0; nt < 8; nt++) {
                acc[nt][0] = __expf(acc[nt][0] - m0); s0 += acc[nt][0];
                acc[nt][1] = __expf(acc[nt][1] - m0); s0 += acc[nt][1];
                acc[nt][2] = __expf(acc[nt][2] - m1); s1 += acc[nt][2];
                acc[nt][3] = __expf(acc[nt][3] - m1); s1 += acc[nt][3];
            }
            s0 += __shfl_xor_sync(0xffffffffu, s0, 1);
            s0 += __shfl_xor_sync(0xffffffffu, s0, 2);
            s1 += __shfl_xor_sync(0xffffffffu, s1, 1);
            s1 += __shfl_xor_sync(0xffffffffu, s1, 2);
            float inv0 = 1.0f / s0, inv1 = 1.0f / s1;

            const __half* gb = g_gateh + (size_t)blk * 32768 + (size_t)head * 4096;
            float* Scm = &smf[SC_OFF + half * 4352];
            #pragma unroll
            for (int nt = 0; nt < 8; nt++) {
                int col = nt * 8 + ec;
                float2 g0 = __half22float2(*(const __half2*)(gb + r0 * 64 + col));
                float2 g1 = __half22float2(*(const __half2*)(gb + (r0 + 8) * 64 + col));
                float2 p0, p1;
                p0.x = acc[nt][0] * inv0 + g0.x;
                p0.y = acc[nt][1] * inv0 + g0.y;
                p1.x = acc[nt][2] * inv1 + g1.x;
                p1.y = acc[nt][3] * inv1 + g1.y;
                *(float2*)&Scm[r0 * 68 + col] = p0;
                *(float2*)&Scm[(r0 + 8) * 68 + col] = p1;
            }
        }
        __syncwarp();                            // own rows: warp-local visibility

        // ---- PV (3xTF32): rows [wg*16,+16) x 32 dims ----
        {
            uint32_t sP = sbase + (SC_OFF + half * 4352) * 4;
            uint32_t sVh = sbase + (VTHI_OFF + half * 2176) * 4;
            uint32_t sVl = sbase + (VTLO_OFF + half * 2176) * 4;
            uint32_t aAddr = sP + (uint32_t)((wg * 16 + a7) * 272 + ahi16);
            uint32_t bAddrH = sVh + (uint32_t)(b7 * 272 + bhi16);
            uint32_t bAddrL = sVl + (uint32_t)(b7 * 272 + bhi16);

            float pacc[4][4];
            #pragma unroll
            for (int nt = 0; nt < 4; nt++)
                #pragma unroll
                for (int t = 0; t < 4; t++) pacc[nt][t] = 0.0f;

            #pragma unroll
            for (int ks = 0; ks < 8; ks++) {
                uint32_t a[4], ah[4], al[4];
                ldsm4(a[0], a[1], a[2], a[3], aAddr + ks * 32);
                #pragma unroll
                for (int t = 0; t < 4; t++) split_tf32(a[t], ah[t], al[t]);
                uint32_t bh[2][4], bl[2][4];
                #pragma unroll
                for (int p = 0; p < 2; p++) {
                    ldsm4(bh[p][0], bh[p][1], bh[p][2], bh[p][3],
                          bAddrH + (uint32_t)(p * 16 * 272) + ks * 32);
                    ldsm4(bl[p][0], bl[p][1], bl[p][2], bl[p][3],
                          bAddrL + (uint32_t)(p * 16 * 272) + ks * 32);
                }
                #pragma unroll
                for (int nt = 0; nt < 4; nt++) {
                    int p = nt >> 1, i0 = (nt & 1) * 2;
                    mma_tf32(pacc[nt][0], pacc[nt][1], pacc[nt][2], pacc[nt][3],
                             ah[0], ah[1], ah[2], ah[3], bh[p][i0], bh[p][i0 + 1]);
                    mma_tf32(pacc[nt][0], pacc[nt][1], pacc[nt][2], pacc[nt][3],
                             ah[0], ah[1], ah[2], ah[3], bl[p][i0], bl[p][i0 + 1]);
                    mma_tf32(pacc[nt][0], pacc[nt][1], pacc[nt][2], pacc[nt][3],
                             al[0], al[1], al[2], al[3], bh[p][i0], bh[p][i0 + 1]);
                }
            }

            float* og0 = g_xm + (size_t)(t0 + r0) * 256 + head * 32;
            float* og1 = g_xm + (size_t)(t0 + r0 + 8) * 256 + head * 32;
            #pragma unroll
            for (int nt = 0; nt < 4; nt++) {
                int col = nt * 8 + ec;
                *(float2*)&og0[col] = make_float2(to_tf32f(pacc[nt][0]),
                                                  to_tf32f(pacc[nt][1]));
                *(float2*)&og1[col] = make_float2(to_tf32f(pacc[nt][2]),
                                                  to_tf32f(pacc[nt][3]));
            }
        }
    }
}

// ---------------- launch ----------------
extern "C" void kernel_launch(void* const* d_in, const int* in_sizes, int n_in,
                              void* d_out, int out_size)
{
    const float* x      = (const float*)d_in[0];
    const float* amask  = (const float*)d_in[1];
    const float* efeat  = (const float*)d_in[2];
    const float* qkv_w  = (const float*)d_in[3];
    const float* qkv_b  = (const float*)d_in[4];
    const float* proj_w = (const float*)d_in[5];
    const float* proj_b = (const float*)d_in[6];
    const float* eg_w1  = (const float*)d_in[7];
    const float* eg_b1  = (const float*)d_in[8];
    const float* eg_w2  = (const float*)d_in[9];
    const float* eg_b2  = (const float*)d_in[10];
    float* out = (float*)d_out;

    void* p_qkv = nullptr; void* p_xc = nullptr; void* p_wc = nullptr;
    void* p_xm  = nullptr; void* p_bias = nullptr;
    cudaGetSymbolAddress(&p_qkv, g_qkv);
    cudaGetSymbolAddress(&p_xc, g_xc);
    cudaGetSymbolAddress(&p_wc, g_wc);
    cudaGetSymbolAddress(&p_xm, g_xm);
    cudaGetSymbolAddress(&p_bias, g_bias);
    float* xc = (float*)p_xc;
    float* wc = (float*)p_wc;

    cudaFuncSetAttribute(attn_mma,
                         cudaFuncAttributeMaxDynamicSharedMemorySize, ATTN_SMEM);
    cudaFuncSetAttribute(gemm_cp,
                         cudaFuncAttributeMaxDynamicSharedMemorySize, GEMM_SMEM);

    // 0) pre-round x and weights to tf32
    cvt_tf32_k<<<(NTOK * CC / 4 + 255) / 256, 256>>>(
        (const float4*)x, (float4*)xc, NTOK * CC / 4);
    cvt_tf32_k<<<(768 * CC / 4 + 255) / 256, 256>>>(
        (const float4*)qkv_w, (float4*)wc, 768 * CC / 4);
    cvt_tf32_k<<<(CC * CC / 4 + 255) / 256, 256>>>(
        (const float4*)proj_w, (float4*)(wc + 768 * CC), CC * CC / 4);

    // 1) QKV projection
    gemm_cp<<<dim3(768 / 128, NTOK / 128), 256, GEMM_SMEM>>>(
        xc, wc, qkv_b, (float*)p_qkv, 768);

    // 2) edge gate + bias matrix
    gate_kernel<<<NBLK, 256>>>(amask, efeat, eg_w1, eg_b1, eg_w2, eg_b2);

    // 3) block attention (register softmax, 2 CTAs/SM)
    attn_mma<<<NBLK, 256, ATTN_SMEM>>>((const float*)p_bias);

    // 4) output projection
    gemm_cp<<<dim3(CC / 128, NTOK / 128), 256, GEMM_SMEM>>>(
        (const float*)p_xm, wc + 768 * CC, proj_b, out, CC);
}

// round 9
// speedup vs baseline: 2.7012x; 1.0158x over previous
#include <cuda_runtime.h>
#include <cuda_fp16.h>
#include <math.h>
#include <cstdint>

// Problem constants
#define BB    4
#define NTOK  32768          // B*N
#define CC    256
#define HH    8
#define HD    32
#define LL    64
#define NBLK  512            // B * NB
#define EGH   16

// ---------------- scratch (device globals; no allocs allowed) ----------------
__device__ float  g_qkv[(size_t)NTOK * 768];           // QKV gemm output (fp32)
__device__ float  g_xc[(size_t)NTOK * CC];             // x pre-rounded to tf32
__device__ float  g_wc[(size_t)(768 + 256) * CC];      // qkv_w | proj_w, tf32-rounded
__device__ __half g_gateh[(size_t)NBLK * 8 * 64 * 64]; // [blk][h][q][k] fp16
__device__ float  g_bias[(size_t)NBLK * 64 * 64];      // [blk][q][k] bias or -1e30
__device__ float  g_xm[(size_t)NTOK * CC];             // attn out (tf32-rounded)

// ======================= PTX helpers =======================
__device__ __forceinline__ uint32_t smem_to_u32(const void* p) {
    uint32_t a;
    asm("{ .reg .u64 t; cvta.to.shared.u64 t, %1; cvt.u32.u64 %0, t; }"
        : "=r"(a) : "l"(p));
    return a;
}

__device__ __forceinline__ void cp_async16(uint32_t smem_addr, const void* gptr) {
    asm volatile("cp.async.cg.shared.global [%0], [%1], 16;"
                 :: "r"(smem_addr), "l"(gptr));
}
#define CP_COMMIT() asm volatile("cp.async.commit_group;" ::: "memory")
#define CP_WAIT(n)  asm volatile("cp.async.wait_group %0;" :: "n"(n) : "memory")

__device__ __forceinline__ void ldsm4(uint32_t& r0, uint32_t& r1, uint32_t& r2,
                                      uint32_t& r3, uint32_t addr) {
    asm volatile("ldmatrix.sync.aligned.m8n8.x4.shared.b16 {%0,%1,%2,%3}, [%4];"
                 : "=r"(r0), "=r"(r1), "=r"(r2), "=r"(r3) : "r"(addr));
}

__device__ __forceinline__ uint32_t to_tf32(uint32_t x) {
    uint32_t y;
    asm("cvt.rna.tf32.f32 %0, %1;" : "=r"(y) : "r"(x));
    return y;
}

__device__ __forceinline__ float to_tf32f(float x) {
    return __uint_as_float(to_tf32(__float_as_uint(x)));
}

__device__ __forceinline__ void split_tf32(uint32_t x, uint32_t& hi, uint32_t& lo) {
    hi = to_tf32(x);
    float r = __uint_as_float(x) - __uint_as_float(hi);
    lo = to_tf32(__float_as_uint(r));
}

__device__ __forceinline__ void split4(float4 v, float4& hi, float4& lo) {
    hi.x = to_tf32f(v.x); lo.x = to_tf32f(v.x - hi.x);
    hi.y = to_tf32f(v.y); lo.y = to_tf32f(v.y - hi.y);
    hi.z = to_tf32f(v.z); lo.z = to_tf32f(v.z - hi.z);
    hi.w = to_tf32f(v.w); lo.w = to_tf32f(v.w - hi.w);
}

__device__ __forceinline__ void mma_tf32(float& c0, float& c1, float& c2, float& c3,
                                         uint32_t a0, uint32_t a1, uint32_t a2, uint32_t a3,
                                         uint32_t b0, uint32_t b1) {
    asm volatile(
        "mma.sync.aligned.m16n8k8.row.col.f32.tf32.tf32.f32 "
        "{%0,%1,%2,%3}, {%4,%5,%6,%7}, {%8,%9}, {%0,%1,%2,%3};"
        : "+f"(c0), "+f"(c1), "+f"(c2), "+f"(c3)
        : "r"(a0), "r"(a1), "r"(a2), "r"(a3), "r"(b0), "r"(b1));
}

// ---------------- tf32 pre-round pass ----------------
__global__ __launch_bounds__(256) void cvt_tf32_k(
    const float4* __restrict__ src, float4* __restrict__ dst, int n4)
{
    int i = blockIdx.x * blockDim.x + threadIdx.x;
    if (i < n4) {
        float4 v = src[i];
        v.x = to_tf32f(v.x); v.y = to_tf32f(v.y);
        v.z = to_tf32f(v.z); v.w = to_tf32f(v.w);
        dst[i] = v;
    }
}

// ============ tf32 GEMM on pre-rounded inputs: Y = X @ W^T + bias ============
#define GEMM_TILE_B 16384                       // 128 rows * 128 bytes
#define GEMM_SMEM  (6 * GEMM_TILE_B)            // 3 stages x (A,B)

__device__ __forceinline__ void load_tile(const float* __restrict__ G, int row0,
                                          int k0, uint32_t s_tile, int tid) {
    #pragma unroll
    for (int i = 0; i < 4; i++) {
        int v = tid + i * 256;                   // 0..1023 float4 slots
        int r = v >> 3, c4 = v & 7;
        uint32_t dst = s_tile + (uint32_t)(r * 128 + ((c4 ^ (r & 7)) << 4));
        cp_async16(dst, G + (size_t)(row0 + r) * 256 + k0 + c4 * 4);
    }
}

__global__ __launch_bounds__(256) void gemm_cp(
    const float* __restrict__ X, const float* __restrict__ W,
    const float* __restrict__ bias, float* __restrict__ Y, int Nn)
{
    extern __shared__ char dsm[];
    uint32_t sbase = smem_to_u32(dsm);

    int tid = threadIdx.x;
    int wid = tid >> 5, lane = tid & 31;
    int warp_m = wid & 1;
    int warp_n = wid >> 1;
    int m0 = blockIdx.y * 128;
    int n0 = blockIdx.x * 128;

    int a_row = warp_m * 64 + (lane & 7) + ((lane >> 3) & 1) * 8;
    int a_hi = lane >> 4;
    int b_row = warp_n * 32 + ((lane >> 4) & 1) * 8 + (lane & 7);
    int b_hi = (lane >> 3) & 1;

    float acc[4][4][4];
    #pragma unroll
    for (int i = 0; i < 4; i++)
        #pragma unroll
        for (int j = 0; j < 4; j++)
            #pragma unroll
            for (int t = 0; t < 4; t++) acc[i][j][t] = 0.0f;

    load_tile(X, m0, 0, sbase, tid);
    load_tile(W, n0, 0, sbase + GEMM_TILE_B, tid);
    CP_COMMIT();
    load_tile(X, m0, 32, sbase + 2 * GEMM_TILE_B, tid);
    load_tile(W, n0, 32, sbase + 3 * GEMM_TILE_B, tid);
    CP_COMMIT();

    #pragma unroll 1
    for (int c = 0; c < 8; c++) {
        if (c < 7) { CP_WAIT(1); } else { CP_WAIT(0); }
        __syncthreads();
        if (c + 2 < 8) {
            uint32_t st = sbase + (uint32_t)(((c + 2) % 3) * 2 * GEMM_TILE_B);
            load_tile(X, m0, (c + 2) * 32, st, tid);
            load_tile(W, n0, (c + 2) * 32, st + GEMM_TILE_B, tid);
            CP_COMMIT();
        }

        uint32_t sA = sbase + (uint32_t)((c % 3) * 2 * GEMM_TILE_B);
        uint32_t sB = sA + GEMM_TILE_B;

        #pragma unroll
        for (int ks = 0; ks < 4; ks++) {
            uint32_t a[4][4], b[2][4];
            #pragma unroll
            for (int mf = 0; mf < 4; mf++) {
                int m = a_row + mf * 16;
                uint32_t addr = sA + (uint32_t)(m * 128
                              + (((2 * ks + a_hi) ^ (m & 7)) << 4));
                ldsm4(a[mf][0], a[mf][1], a[mf][2], a[mf][3], addr);
            }
            #pragma unroll
            for (int p = 0; p < 2; p++) {
                int n = b_row + p * 16;
                uint32_t addr = sB + (uint32_t)(n * 128
                              + (((2 * ks + b_hi) ^ (n & 7)) << 4));
                ldsm4(b[p][0], b[p][1], b[p][2], b[p][3], addr);
            }
            #pragma unroll
            for (int mf = 0; mf < 4; mf++)
                #pragma unroll
                for (int nf = 0; nf < 4; nf++)
                    mma_tf32(acc[mf][nf][0], acc[mf][nf][1],
                             acc[mf][nf][2], acc[mf][nf][3],
                             a[mf][0], a[mf][1], a[mf][2], a[mf][3],
                             b[nf >> 1][(nf & 1) * 2], b[nf >> 1][(nf & 1) * 2 + 1]);
        }
    }

    int er = lane >> 2, ec = (lane & 3) * 2;
    #pragma unroll
    for (int mf = 0; mf < 4; mf++) {
        int row = m0 + warp_m * 64 + mf * 16 + er;
        #pragma unroll
        for (int nf = 0; nf < 4; nf++) {
            int col = n0 + warp_n * 32 + nf * 8 + ec;
            float2 bv = *(const float2*)&bias[col];
            float2 o0, o1;
            o0.x = acc[mf][nf][0] + bv.x;
            o0.y = acc[mf][nf][1] + bv.y;
            o1.x = acc[mf][nf][2] + bv.x;
            o1.y = acc[mf][nf][3] + bv.y;
            *(float2*)&Y[(size_t)row * Nn + col] = o0;
            *(float2*)&Y[(size_t)(row + 8) * Nn + col] = o1;
        }
    }
}

// ------- gate kernel: fp16 g[blk][h][q][k] + fp32 bias[blk][q][k] -------
__global__ __launch_bounds__(256) void gate_kernel(
    const float* __restrict__ mask_g, const float* __restrict__ ef,
    const float* __restrict__ w1, const float* __restrict__ b1,
    const float* __restrict__ w2, const float* __restrict__ b2)
{
    __shared__ float sm[64 * 64];
    __shared__ float sw1[64], sb1[16], sw2[128], sb2[8];
    int blk = blockIdx.x;
    int tid = threadIdx.x;

    const float* mbase = mask_g + (size_t)blk * 4096;
    #pragma unroll
    for (int i = 0; i < 16; i++) sm[tid + i * 256] = mbase[tid + i * 256];
    if (tid < 64)  sw1[tid] = w1[tid];
    if (tid < 16)  sb1[tid] = b1[tid];
    if (tid < 128) sw2[tid] = w2[tid];
    if (tid < 8)   sb2[tid] = b2[tid];
    __syncthreads();

    if (tid < 64) {
        float s = 0.0f;
        for (int k = 0; k < 64; k++) s += sm[tid * 64 + k];
        if (s < 1.0f) sm[tid * 64 + tid] = 1.0f;
    }
    __syncthreads();

    for (int it = 0; it < 16; it++) {
        int idx = tid + it * 256;
        int q = idx >> 6, k = idx & 63;
        float m = sm[idx];
        float out[8];
        float bias;
        if (m == 0.0f) {
            bias = -1e30f;
            #pragma unroll
            for (int h = 0; h < 8; h++) out[h] = 0.0f;
        } else {
            float e0, e1, e2, e3;
            if (q == k) { e0 = e1 = e2 = 0.0f; e3 = 1.0f; }
            else {
                float4 ev = *(const float4*)(ef + ((size_t)blk * 4096 + idx) * 4);
                e0 = ev.x; e1 = ev.y; e2 = ev.z; e3 = ev.w;
            }
            bias = e3;
            float hh[16];
            #pragma unroll
            for (int j = 0; j < 16; j++) {
                float t = sb1[j] + sw1[j * 4] * e0 + sw1[j * 4 + 1] * e1
                        + sw1[j * 4 + 2] * e2 + sw1[j * 4 + 3] * e3;
                hh[j] = 0.5f * t * (1.0f + erff(t * 0.70710678118654752f));
            }
            #pragma unroll
            for (int h = 0; h < 8; h++) {
                float s = sb2[h];
                #pragma unroll
                for (int j = 0; j < 16; j++) s += sw2[h * 16 + j] * hh[j];
                out[h] = s;
            }
        }
        g_bias[(size_t)blk * 4096 + idx] = bias;
        __half* gp = g_gateh + (size_t)blk * 32768 + idx;
        #pragma unroll
        for (int h = 0; h < 8; h++) gp[h * 4096] = __float2half_rn(out[h]);
    }
}

// ------- attention kernel: register softmax, pre-split K, 2 CTAs/SM -------
#define SC_OFF    0                 // [2][64][68]  P (probs+gate)
#define QH_OFF    8704              // [2][64][36]  Q raw fp32
#define KHI_OFF   13312             // [2][64][36]  K tf32-hi
#define KLO_OFF   17920             // [2][64][36]  K tf32-lo
#define VTHI_OFF  22528             // [2][32][68]  V^T tf32
#define ATTN_FLOATS 26880
#define ATTN_SMEM (ATTN_FLOATS * 4) // 105 KB -> 2 CTAs/SM

__global__ __launch_bounds__(256, 2) void attn_mma(
    const float* __restrict__ bias_g)
{
    extern __shared__ float smf[];
    uint32_t sbase = smem_to_u32(smf);

    int blk = blockIdx.x;
    int tid = threadIdx.x;
    int wid = tid >> 5, lane = tid & 31;
    int half = wid >> 2;
    int wg = wid & 3;
    int t0 = blk * 64;

    const float scale = 0.17677669529663687f;

    int a7 = (lane & 7) + ((lane >> 3) & 1) * 8;
    int ahi16 = (lane >> 4) * 16;
    int b7 = (lane & 7) + ((lane >> 4) & 1) * 8;
    int bhi16 = ((lane >> 3) & 1) * 16;
    int er = lane >> 2, ec = (lane & 3) * 2;

    #pragma unroll 1
    for (int it = 0; it < 4; it++) {
        if (it) __syncthreads();                 // prev iter done with tiles

        // ---- stage Q raw, K pre-split hi/lo, V^T tf32 for heads 2it, 2it+1 ----
        #pragma unroll
        for (int j = 0; j < 4; j++) {
            int idx = tid + j * 256;
            int sh = idx >> 9;
            int rem = idx & 511;
            int t = rem >> 3, c4 = rem & 7;
            int head = it * 2 + sh;
            const float* src = g_qkv + (size_t)(t0 + t) * 768 + head * 32 + c4 * 4;
            float4 qv = *(const float4*)(src);
            float4 kv = *(const float4*)(src + 256);
            float4 vv = *(const float4*)(src + 512);
            *(float4*)&smf[QH_OFF + sh * 2304 + t * 36 + c4 * 4] = qv;
            float4 khi, klo; split4(kv, khi, klo);
            *(float4*)&smf[KHI_OFF + sh * 2304 + t * 36 + c4 * 4] = khi;
            *(float4*)&smf[KLO_OFF + sh * 2304 + t * 36 + c4 * 4] = klo;
            float* vh = &smf[VTHI_OFF + sh * 2176 + (c4 * 4) * 68 + t];
            vh[0]   = to_tf32f(vv.x);
            vh[68]  = to_tf32f(vv.y);
            vh[136] = to_tf32f(vv.z);
            vh[204] = to_tf32f(vv.w);
        }
        __syncthreads();

        int head = it * 2 + half;

        // ---- QK^T (3xTF32), rows [wg*16,+16) x all 64 cols ----
        float acc[8][4];
        #pragma unroll
        for (int nt = 0; nt < 8; nt++)
            #pragma unroll
            for (int t = 0; t < 4; t++) acc[nt][t] = 0.0f;
        {
            uint32_t sQ  = sbase + (QH_OFF + half * 2304) * 4;
            uint32_t sKh = sbase + (KHI_OFF + half * 2304) * 4;
            uint32_t sKl = sbase + (KLO_OFF + half * 2304) * 4;
            uint32_t aAddr  = sQ + (uint32_t)((wg * 16 + a7) * 144 + ahi16);
            uint32_t bAddrH = sKh + (uint32_t)(b7 * 144 + bhi16);
            uint32_t bAddrL = sKl + (uint32_t)(b7 * 144 + bhi16);

            #pragma unroll
            for (int ks = 0; ks < 4; ks++) {
                uint32_t a[4], ah[4], al[4];
                ldsm4(a[0], a[1], a[2], a[3], aAddr + ks * 32);
                #pragma unroll
                for (int t = 0; t < 4; t++) split_tf32(a[t], ah[t], al[t]);
                uint32_t bh[4][4], bl[4][4];
                #pragma unroll
                for (int p = 0; p < 4; p++) {
                    ldsm4(bh[p][0], bh[p][1], bh[p][2], bh[p][3],
                          bAddrH + (uint32_t)(p * 16 * 144) + ks * 32);
                    ldsm4(bl[p][0], bl[p][1], bl[p][2], bl[p][3],
                          bAddrL + (uint32_t)(p * 16 * 144) + ks * 32);
                }
                #pragma unroll
                for (int nt = 0; nt < 8; nt++) {
                    int p = nt >> 1, i0 = (nt & 1) * 2;
                    mma_tf32(acc[nt][0], acc[nt][1], acc[nt][2], acc[nt][3],
                             ah[0], ah[1], ah[2], ah[3], bh[p][i0], bh[p][i0 + 1]);
                    mma_tf32(acc[nt][0], acc[nt][1], acc[nt][2], acc[nt][3],
                             ah[0], ah[1], ah[2], ah[3], bl[p][i0], bl[p][i0 + 1]);
                    mma_tf32(acc[nt][0], acc[nt][1], acc[nt][2], acc[nt][3],
                             al[0], al[1], al[2], al[3], bh[p][i0], bh[p][i0 + 1]);
                }
            }
        }

        // ---- bias + softmax + gate, entirely in registers ----
        int r0 = wg * 16 + er;
        {
            const float* bb = bias_g + (size_t)blk * 4096;
            float m0 = -3.0e38f, m1 = -3.0e38f;
            #pragma unroll
            for (int nt = 0; nt < 8; nt++) {
                int col = nt * 8 + ec;
                float2 b0 = *(const float2*)&bb[r0 * 64 + col];
                float2 b1 = *(const float2*)&bb[(r0 + 8) * 64 + col];
                acc[nt][0] = acc[nt][0] * scale + b0.x;
                acc[nt][1] = acc[nt][1] * scale + b0.y;
                acc[nt][2] = acc[nt][2] * scale + b1.x;
                acc[nt][3] = acc[nt][3] * scale + b1.y;
                m0 = fmaxf(m0, fmaxf(acc[nt][0], acc[nt][1]));
                m1 = fmaxf(m1, fmaxf(acc[nt][2], acc[nt][3]));
            }
            m0 = fmaxf(m0, __shfl_xor_sync(0xffffffffu, m0, 1));
            m0 = fmaxf(m0, __shfl_xor_sync(0xffffffffu, m0, 2));
            m1 = fmaxf(m1, __shfl_xor_sync(0xffffffffu, m1, 1));
            m1 = fmaxf(m1, __shfl_xor_sync(0xffffffffu, m1, 2));
            float s0 = 0.0f, s1 = 0.0f;
            #pragma unroll
            for (int nt = 0; nt < 8; nt++) {
                acc[nt][0] = __expf(acc[nt][0] - m0); s0 += acc[nt][0];
                acc[nt][1] = __expf(acc[nt][1] - m0); s0 += acc[nt][1];
                acc[nt][2] = __expf(acc[nt][2] - m1); s1 += acc[nt][2];
                acc[nt][3] = __expf(acc[nt][3] - m1); s1 += acc[nt][3];
            }
            s0 += __shfl_xor_sync(0xffffffffu, s0, 1);
            s0 += __shfl_xor_sync(0xffffffffu, s0, 2);
            s1 += __shfl_xor_sync(0xffffffffu, s1, 1);
            s1 += __shfl_xor_sync(0xffffffffu, s1, 2);
            float inv0 = 1.0f / s0, inv1 = 1.0f / s1;

            const __half* gb = g_gateh + (size_t)blk * 32768 + (size_t)head * 4096;
            float* Scm = &smf[SC_OFF + half * 4352];
            #pragma unroll
            for (int nt = 0; nt < 8; nt++) {
                int col = nt * 8 + ec;
                float2 g0 = __half22float2(*(const __half2*)(gb + r0 * 64 + col));
                float2 g1 = __half22float2(*(const __half2*)(gb + (r0 + 8) * 64 + col));
                float2 p0, p1;
                p0.x = acc[nt][0] * inv0 + g0.x;
                p0.y = acc[nt][1] * inv0 + g0.y;
                p1.x = acc[nt][2] * inv1 + g1.x;
                p1.y = acc[nt][3] * inv1 + g1.y;
                *(float2*)&Scm[r0 * 68 + col] = p0;
                *(float2*)&Scm[(r0 + 8) * 68 + col] = p1;
            }
        }
        __syncwarp();                            // own rows: warp-local visibility

        // ---- PV (2-term: P split, V plain tf32): rows [wg*16,+16) x 32 dims ----
        {
            uint32_t sP  = sbase + (SC_OFF + half * 4352) * 4;
            uint32_t sVh = sbase + (VTHI_OFF + half * 2176) * 4;
            uint32_t aAddr  = sP + (uint32_t)((wg * 16 + a7) * 272 + ahi16);
            uint32_t bAddrH = sVh + (uint32_t)(b7 * 272 + bhi16);

            float pacc[4][4];
            #pragma unroll
            for (int nt = 0; nt < 4; nt++)
                #pragma unroll
                for (int t = 0; t < 4; t++) pacc[nt][t] = 0.0f;

            #pragma unroll
            for (int ks = 0; ks < 8; ks++) {
                uint32_t a[4], ah[4], al[4];
                ldsm4(a[0], a[1], a[2], a[3], aAddr + ks * 32);
                #pragma unroll
                for (int t = 0; t < 4; t++) split_tf32(a[t], ah[t], al[t]);
                uint32_t bh[2][4];
                #pragma unroll
                for (int p = 0; p < 2; p++)
                    ldsm4(bh[p][0], bh[p][1], bh[p][2], bh[p][3],
                          bAddrH + (uint32_t)(p * 16 * 272) + ks * 32);
                #pragma unroll
                for (int nt = 0; nt < 4; nt++) {
                    int p = nt >> 1, i0 = (nt & 1) * 2;
                    mma_tf32(pacc[nt][0], pacc[nt][1], pacc[nt][2], pacc[nt][3],
                             ah[0], ah[1], ah[2], ah[3], bh[p][i0], bh[p][i0 + 1]);
                    mma_tf32(pacc[nt][0], pacc[nt][1], pacc[nt][2], pacc[nt][3],
                             al[0], al[1], al[2], al[3], bh[p][i0], bh[p][i0 + 1]);
                }
            }

            float* og0 = g_xm + (size_t)(t0 + r0) * 256 + head * 32;
            float* og1 = g_xm + (size_t)(t0 + r0 + 8) * 256 + head * 32;
            #pragma unroll
            for (int nt = 0; nt < 4; nt++) {
                int col = nt * 8 + ec;
                *(float2*)&og0[col] = make_float2(to_tf32f(pacc[nt][0]),
                                                  to_tf32f(pacc[nt][1]));
                *(float2*)&og1[col] = make_float2(to_tf32f(pacc[nt][2]),
                                                  to_tf32f(pacc[nt][3]));
            }
        }
    }
}

// ---------------- launch ----------------
extern "C" void kernel_launch(void* const* d_in, const int* in_sizes, int n_in,
                              void* d_out, int out_size)
{
    const float* x      = (const float*)d_in[0];
    const float* amask  = (const float*)d_in[1];
    const float* efeat  = (const float*)d_in[2];
    const float* qkv_w  = (const float*)d_in[3];
    const float* qkv_b  = (const float*)d_in[4];
    const float* proj_w = (const float*)d_in[5];
    const float* proj_b = (const float*)d_in[6];
    const float* eg_w1  = (const float*)d_in[7];
    const float* eg_b1  = (const float*)d_in[8];
    const float* eg_w2  = (const float*)d_in[9];
    const float* eg_b2  = (const float*)d_in[10];
    float* out = (float*)d_out;

    void* p_qkv = nullptr; void* p_xc = nullptr; void* p_wc = nullptr;
    void* p_xm  = nullptr; void* p_bias = nullptr;
    cudaGetSymbolAddress(&p_qkv, g_qkv);
    cudaGetSymbolAddress(&p_xc, g_xc);
    cudaGetSymbolAddress(&p_wc, g_wc);
    cudaGetSymbolAddress(&p_xm, g_xm);
    cudaGetSymbolAddress(&p_bias, g_bias);
    float* xc = (float*)p_xc;
    float* wc = (float*)p_wc;

    cudaFuncSetAttribute(attn_mma,
                         cudaFuncAttributeMaxDynamicSharedMemorySize, ATTN_SMEM);
    cudaFuncSetAttribute(gemm_cp,
                         cudaFuncAttributeMaxDynamicSharedMemorySize, GEMM_SMEM);

    // 0) pre-round x and weights to tf32
    cvt_tf32_k<<<(NTOK * CC / 4 + 255) / 256, 256>>>(
        (const float4*)x, (float4*)xc, NTOK * CC / 4);
    cvt_tf32_k<<<(768 * CC / 4 + 255) / 256, 256>>>(
        (const float4*)qkv_w, (float4*)wc, 768 * CC / 4);
    cvt_tf32_k<<<(CC * CC / 4 + 255) / 256, 256>>>(
        (const float4*)proj_w, (float4*)(wc + 768 * CC), CC * CC / 4);

    // 1) QKV projection
    gemm_cp<<<dim3(768 / 128, NTOK / 128), 256, GEMM_SMEM>>>(
        xc, wc, qkv_b, (float*)p_qkv, 768);

    // 2) edge gate + bias matrix
    gate_kernel<<<NBLK, 256>>>(amask, efeat, eg_w1, eg_b1, eg_w2, eg_b2);

    // 3) block attention (pre-split K, register softmax, 2 CTAs/SM)
    attn_mma<<<NBLK, 256, ATTN_SMEM>>>((const float*)p_bias);

    // 4) output projection
    gemm_cp<<<dim3(CC / 128, NTOK / 128), 256, GEMM_SMEM>>>(
        (const float*)p_xm, wc + 768 * CC, proj_b, out, CC);
}